// round 10
// baseline (speedup 1.0000x reference)
#include <cuda_runtime.h>
#include <stdint.h>

#define BATCH 512
#define HIDN  196
#define RECN  488
#define G3N   1464
#define G3P   1536     // gate-padded: 3 x 512
#define KPH   208      // HIDN padded to mult of 16
#define KPR   496      // RECN padded to mult of 16
#define NCN   35
#define NC3   105
#define NCP   128
#define TN    120
#define BHP   (BATCH*KPR)
#define GRID_P 128

typedef unsigned long long ull;

// ---------------- f32x2 helpers ----------------
__device__ __forceinline__ ull dup2(float x) {
    ull r; asm("mov.b64 %0, {%1, %1};" : "=l"(r) : "f"(x)); return r;
}
__device__ __forceinline__ void fma2(ull& d, ull a, ull b) {
    asm("fma.rn.f32x2 %0, %1, %2, %0;" : "+l"(d) : "l"(a), "l"(b));
}
__device__ __forceinline__ float2 unpk(ull v) {
    float2 r; asm("mov.b64 {%0, %1}, %2;" : "=f"(r.x), "=f"(r.y) : "l"(v)); return r;
}
__device__ __forceinline__ float sigmf(float x) { return 1.f / (1.f + __expf(-x)); }
__device__ __forceinline__ float tanhfast(float x) { return 1.f - 2.f / (__expf(2.f * x) + 1.f); }

__device__ __forceinline__ uint32_t smaddr(const void* p) {
    return (uint32_t)__cvta_generic_to_shared(p);
}
__device__ __forceinline__ void cp16(void* dst, const void* src) {
    asm volatile("cp.async.ca.shared.global [%0], [%1], 16;" :: "r"(smaddr(dst)), "l"(src));
}
__device__ __forceinline__ void cp8(void* dst, const void* src) {
    asm volatile("cp.async.ca.shared.global [%0], [%1], 8;" :: "r"(smaddr(dst)), "l"(src));
}
__device__ __forceinline__ void cp_commit() { asm volatile("cp.async.commit_group;"); }
__device__ __forceinline__ void cp_wait0()  { asm volatile("cp.async.wait_group 0;" ::: "memory"); }
__device__ __forceinline__ void cp_wait1()  { asm volatile("cp.async.wait_group 1;" ::: "memory"); }

__device__ __forceinline__ unsigned ld_acq(unsigned* p) {
    unsigned v;
    asm volatile("ld.acquire.gpu.global.b32 %0, [%1];" : "=r"(v) : "l"(p) : "memory");
    return v;
}

// ---------------- scratch ----------------
__device__ float g_z1 [BATCH*HIDN];
__device__ float g_z2 [BATCH*KPH];
__device__ float g_xg0[(size_t)BATCH*G3P];
__device__ float g_X0 [(size_t)TN*BATCH*KPR];
__device__ float g_X1 [(size_t)TN*BATCH*KPR];
__device__ float g_XGc[(size_t)TN*BATCH*NCP];
__device__ float g_WtD0[HIDN*HIDN];
__device__ float g_WtD1[HIDN*HIDN];
__device__ float g_Wt0x[(size_t)KPH*G3P];
__device__ float g_Wt0h[(size_t)KPR*G3P];
__device__ float g_Wt1hx[(size_t)2*KPR*G3P];   // rows [0,496): Whh1ᵀ, rows [496,992): Wih1ᵀ
__device__ float g_Wtc [(size_t)KPR*NCP];

// grid-barrier state (monotonic generation: replay-safe, never reset)
__device__ unsigned g_barGen = 0;
__device__ unsigned g_barCnt = 0;

// ---------------- fused transpose/pack (7 jobs) ----------------
__global__ void trans_all(
    const float* __restrict__ W0,  const float* __restrict__ W1,
    const float* __restrict__ Wih0,const float* __restrict__ Whh0,
    const float* __restrict__ Wih1,const float* __restrict__ Whh1,
    const float* __restrict__ Wc,
    float* __restrict__ WtD0, float* __restrict__ WtD1,
    float* __restrict__ Wt0x, float* __restrict__ Wt0h,
    float* __restrict__ Wt1x, float* __restrict__ Wt1h,
    float* __restrict__ Wtc)
{
    int j = blockIdx.z;
    const float* src; float* dst;
    int DR, DC, SK, NV, gate;
    switch (j) {
      case 0: src=W0;   dst=WtD0; DR=HIDN; DC=HIDN; SK=HIDN; NV=HIDN; gate=0; break;
      case 1: src=W1;   dst=WtD1; DR=HIDN; DC=HIDN; SK=HIDN; NV=HIDN; gate=0; break;
      case 2: src=Wih0; dst=Wt0x; DR=KPH;  DC=G3P;  SK=HIDN; NV=RECN; gate=1; break;
      case 3: src=Whh0; dst=Wt0h; DR=KPR;  DC=G3P;  SK=RECN; NV=RECN; gate=1; break;
      case 4: src=Wih1; dst=Wt1x; DR=KPR;  DC=G3P;  SK=RECN; NV=RECN; gate=1; break;
      case 5: src=Whh1; dst=Wt1h; DR=KPR;  DC=G3P;  SK=RECN; NV=RECN; gate=1; break;
      default:src=Wc;   dst=Wtc;  DR=KPR;  DC=NCP;  SK=RECN; NV=NC3;  gate=0; break;
    }
    int r0 = blockIdx.y * 32, c0 = blockIdx.x * 32;
    if (r0 >= DR || c0 >= DC) return;
    __shared__ float tile[32][33];
    int tx = threadIdx.x, ty = threadIdx.y;
    for (int i = ty; i < 32; i += 8) {
        int c = c0 + i, k = r0 + tx;
        float v = 0.f;
        if (c < DC && k < SK) {
            int n  = gate ? (c & 511) : c;
            int sr = gate ? ((c >> 9) * RECN + n) : c;
            if (n < NV) v = src[(size_t)sr * SK + k];
        }
        tile[i][tx] = v;
    }
    __syncthreads();
    for (int i = ty; i < 32; i += 8) {
        int r = r0 + i, c = c0 + tx;
        if (r < DR && c < DC) dst[(size_t)r * DC + c] = tile[tx][i];
    }
}

// ---------------- small GEMM for dense+BN ----------------
__global__ __launch_bounds__(256)
void gemm_naive(const float* __restrict__ A, const float* __restrict__ Bt,
                const float* __restrict__ bias, const float* __restrict__ gamma,
                const float* __restrict__ beta, float* __restrict__ C,
                int M, int N, int K, int ldc) {
    __shared__ float As[16][132];
    __shared__ float Bs[16][128];
    int tid = threadIdx.x;
    int tx = tid & 15, ty = tid >> 4;
    int rowBase = blockIdx.y * 128, colBase = blockIdx.x * 128;
    ull acc[8][4];
#pragma unroll
    for (int i = 0; i < 8; i++)
#pragma unroll
        for (int j = 0; j < 4; j++) acc[i][j] = 0ULL;

    for (int k0 = 0; k0 < K; k0 += 16) {
        {
            int kk = tid & 15, m0 = tid >> 4;
#pragma unroll
            for (int l = 0; l < 8; l++) {
                int m = m0 + l * 16;
                float v = 0.f;
                if (k0 + kk < K) v = A[(size_t)(rowBase + m) * K + k0 + kk];
                As[kk][m] = v;
            }
        }
        {
            int c = tid & 127, kb = tid >> 7;
#pragma unroll
            for (int l = 0; l < 8; l++) {
                int kk = kb + l * 2;
                float v = 0.f;
                if ((k0 + kk) < K && (colBase + c) < N)
                    v = Bt[(size_t)(k0 + kk) * N + colBase + c];
                Bs[kk][c] = v;
            }
        }
        __syncthreads();
#pragma unroll
        for (int kk = 0; kk < 16; kk++) {
            float4 av0 = *(const float4*)&As[kk][ty * 8];
            float4 av1 = *(const float4*)&As[kk][ty * 8 + 4];
            ull a2[8];
            a2[0]=dup2(av0.x); a2[1]=dup2(av0.y); a2[2]=dup2(av0.z); a2[3]=dup2(av0.w);
            a2[4]=dup2(av1.x); a2[5]=dup2(av1.y); a2[6]=dup2(av1.z); a2[7]=dup2(av1.w);
            const ulonglong2* bp = (const ulonglong2*)&Bs[kk][tx * 8];
            ulonglong2 bv0 = bp[0], bv1 = bp[1];
            ull b2[4] = {bv0.x, bv0.y, bv1.x, bv1.y};
#pragma unroll
            for (int i = 0; i < 8; i++)
#pragma unroll
                for (int j = 0; j < 4; j++) fma2(acc[i][j], a2[i], b2[j]);
        }
        __syncthreads();
    }
    const float invs = 0.99950037f;   // 1/sqrt(1.001)
#pragma unroll
    for (int i = 0; i < 8; i++) {
        int row = rowBase + ty * 8 + i;
        if (row >= M) continue;
#pragma unroll
        for (int j = 0; j < 4; j++) {
            float2 p = unpk(acc[i][j]);
#pragma unroll
            for (int s = 0; s < 2; s++) {
                int col = colBase + tx * 8 + j * 2 + s;
                if (col < N) {
                    float v = (s == 0) ? p.x : p.y;
                    v += bias[col];
                    v = gamma[col] * (v * invs) + beta[col];
                    C[(size_t)row * ldc + col] = v;
                }
            }
        }
    }
}

// ---------------- pipelined 128x128 GEMM (padded, unguarded hot loop) ----------------
__global__ __launch_bounds__(256, 2)
void gemmP(const float* __restrict__ A, int lda, int KP,
           const float* __restrict__ B, int NP,
           const float* __restrict__ bias, int gate, int Nvalid,
           float* __restrict__ C)
{
    __shared__ float As[2][16][132];
    __shared__ float Bs[2][16][128];
    int tid = threadIdx.x;
    int tx = tid & 15, ty = tid >> 4;
    size_t rowBase = (size_t)blockIdx.y * 128;
    int colBase = blockIdx.x * 128;
    int NT = KP >> 4;

    ull acc[8][4];
#pragma unroll
    for (int i = 0; i < 8; i++)
#pragma unroll
        for (int j = 0; j < 4; j++) acc[i][j] = 0ULL;

    int arow[2], akq[2], bkk[2], bc4[2];
#pragma unroll
    for (int l = 0; l < 2; l++) {
        int idx = tid + l * 256;
        arow[l] = idx >> 2;  akq[l] = idx & 3;
        bkk[l]  = idx >> 5;  bc4[l] = idx & 31;
    }

    float4 a0[2];
#pragma unroll
    for (int l = 0; l < 2; l++)
        a0[l] = *(const float4*)(A + (rowBase + arow[l]) * lda + akq[l] * 4);
#pragma unroll
    for (int l = 0; l < 2; l++)
        cp16(&Bs[0][bkk[l]][bc4[l] * 4], B + (size_t)bkk[l] * NP + colBase + bc4[l] * 4);
    cp_commit();
#pragma unroll
    for (int l = 0; l < 2; l++) {
        float f[4] = {a0[l].x, a0[l].y, a0[l].z, a0[l].w};
#pragma unroll
        for (int q = 0; q < 4; q++) As[0][akq[l] * 4 + q][arow[l]] = f[q];
    }

    for (int kt = 0; kt < NT; kt++) {
        int cb = kt & 1, nb = (kt + 1) & 1;
        float4 an[2];
        bool more = (kt + 1 < NT);
        if (more) {
#pragma unroll
            for (int l = 0; l < 2; l++)
                an[l] = *(const float4*)(A + (rowBase + arow[l]) * lda + (kt + 1) * 16 + akq[l] * 4);
        }
        cp_wait0();
        __syncthreads();
        if (more) {
#pragma unroll
            for (int l = 0; l < 2; l++)
                cp16(&Bs[nb][bkk[l]][bc4[l] * 4],
                     B + (size_t)((kt + 1) * 16 + bkk[l]) * NP + colBase + bc4[l] * 4);
            cp_commit();
        }
#pragma unroll
        for (int kk = 0; kk < 16; kk++) {
            float4 av0 = *(const float4*)&As[cb][kk][ty * 8];
            float4 av1 = *(const float4*)&As[cb][kk][ty * 8 + 4];
            ull a2[8];
            a2[0]=dup2(av0.x); a2[1]=dup2(av0.y); a2[2]=dup2(av0.z); a2[3]=dup2(av0.w);
            a2[4]=dup2(av1.x); a2[5]=dup2(av1.y); a2[6]=dup2(av1.z); a2[7]=dup2(av1.w);
            const ulonglong2* bp = (const ulonglong2*)&Bs[cb][kk][tx * 8];
            ulonglong2 bv0 = bp[0], bv1 = bp[1];
            ull b2[4] = {bv0.x, bv0.y, bv1.x, bv1.y};
#pragma unroll
            for (int i = 0; i < 8; i++)
#pragma unroll
                for (int j = 0; j < 4; j++) fma2(acc[i][j], a2[i], b2[j]);
        }
        __syncthreads();
        if (more) {
#pragma unroll
            for (int l = 0; l < 2; l++) {
                float f[4] = {an[l].x, an[l].y, an[l].z, an[l].w};
#pragma unroll
                for (int q = 0; q < 4; q++) As[nb][akq[l] * 4 + q][arow[l]] = f[q];
            }
        }
    }

#pragma unroll
    for (int i = 0; i < 8; i++) {
        size_t row = rowBase + ty * 8 + i;
#pragma unroll
        for (int j = 0; j < 4; j++) {
            float2 p = unpk(acc[i][j]);
#pragma unroll
            for (int s = 0; s < 2; s++) {
                int col = colBase + tx * 8 + j * 2 + s;
                float v = (s == 0) ? p.x : p.y;
                if (bias) {
                    if (gate) {
                        int n = col & 511;
                        if (n < RECN) v += bias[(col >> 9) * RECN + n];
                    } else if (col < Nvalid) {
                        v += bias[col];
                    }
                }
                C[row * NP + col] = v;
            }
        }
    }
}

// ---------------- 16-k MMA tile (aN selects the n-gate accumulator) ----------------
__device__ __forceinline__ void gru_mma16(
    const ull (*Ad)[64], const float (*Ws)[16][32],
    ull (&a0)[4], ull (&a1)[4], ull (&aN)[4], int tx, int ty)
{
#pragma unroll
    for (int kk = 0; kk < 16; kk++) {
        const ulonglong2* ap = (const ulonglong2*)&Ad[kk][ty * 4];
        ulonglong2 v0 = ap[0], v1 = ap[1];
        ull a2[4] = {v0.x, v0.y, v1.x, v1.y};
        ull w0 = *(const ull*)&Ws[0][kk][tx * 2];
        ull w1 = *(const ull*)&Ws[1][kk][tx * 2];
        ull w2 = *(const ull*)&Ws[2][kk][tx * 2];
#pragma unroll
        for (int i = 0; i < 4; i++) {
            fma2(a0[i], a2[i], w0);
            fma2(a1[i], a2[i], w1);
            fma2(aN[i], a2[i], w2);
        }
    }
}

// ---------------- GRU0 tile: 3-stage W pipeline + 2-ahead A prefetch ----------------
__device__ __forceinline__ void gru0_tile(
    ull (&Ad)[2][16][64], float (&Ws)[3][3][16][32],
    const float* __restrict__ h0prev, const float* __restrict__ xg0v,
    const float* __restrict__ W0, const float* __restrict__ bhh0,
    float* __restrict__ h0out,
    int tx, int ty, int rowBase, int colBase, int arow, int akq, int wkk, int wc2)
{
    ull acc[3][4];
#pragma unroll
    for (int g = 0; g < 3; g++)
#pragma unroll
        for (int i = 0; i < 4; i++) acc[g][i] = 0ULL;

    if (h0prev) {
        const float* Abase = h0prev + (size_t)(rowBase + arow) * KPR + akq * 4;
        const float* Wbase = W0 + colBase + wc2 * 2;
        const int NT = KPR / 16;   // 31

        // prologue: A tile 0 -> Ad[0]; A tile 1 -> regs; W tiles 0,1 -> Ws[0],Ws[1]
        float4 aC = *(const float4*)(Abase);
        float4 aN1 = *(const float4*)(Abase + 16);
#pragma unroll
        for (int g = 0; g < 3; g++)
            cp8(&Ws[0][g][wkk][wc2 * 2], Wbase + (size_t)wkk * G3P + g * 512);
        cp_commit();
#pragma unroll
        for (int g = 0; g < 3; g++)
            cp8(&Ws[1][g][wkk][wc2 * 2], Wbase + (size_t)(16 + wkk) * G3P + g * 512);
        cp_commit();
        {
            float f[4] = {aC.x, aC.y, aC.z, aC.w};
#pragma unroll
            for (int q = 0; q < 4; q++) Ad[0][akq * 4 + q][arow] = dup2(f[q]);
        }
        int sC = 0, sP = 2;   // consume / produce stage indices
        for (int kt = 0; kt < NT; kt++) {
            float4 aN2;
            if (kt + 2 < NT) aN2 = *(const float4*)(Abase + (kt + 2) * 16);
            cp_wait1();            // W for tile kt (issued at kt-2) complete
            __syncthreads();
            if (kt + 2 < NT) {
#pragma unroll
                for (int g = 0; g < 3; g++)
                    cp8(&Ws[sP][g][wkk][wc2 * 2],
                        Wbase + (size_t)((kt + 2) * 16 + wkk) * G3P + g * 512);
            }
            cp_commit();           // always commit (empty groups legal)
            gru_mma16(Ad[kt & 1], Ws[sC], acc[0], acc[1], acc[2], tx, ty);
            if (kt + 1 < NT) {
                float f[4] = {aN1.x, aN1.y, aN1.z, aN1.w};
#pragma unroll
                for (int q = 0; q < 4; q++) Ad[(kt + 1) & 1][akq * 4 + q][arow] = dup2(f[q]);
            }
            aN1 = aN2;
            sC = (sC == 2) ? 0 : sC + 1;
            sP = (sP == 2) ? 0 : sP + 1;
        }
    }
    int col = colBase + tx * 2;
    if (col < RECN) {
        float2 bh0 = *(const float2*)(bhh0 + 0 * RECN + col);
        float2 bh1v = *(const float2*)(bhh0 + 1 * RECN + col);
        float2 bh2 = *(const float2*)(bhh0 + 2 * RECN + col);
#pragma unroll
        for (int i = 0; i < 4; i++) {
            int b = rowBase + ty * 4 + i;
            const float* xgb = xg0v + (size_t)b * G3P;
            float2 xr = *(const float2*)(xgb + 0 * 512 + col);
            float2 xz = *(const float2*)(xgb + 1 * 512 + col);
            float2 xn = *(const float2*)(xgb + 2 * 512 + col);
            float2 hr = unpk(acc[0][i]);
            float2 hz = unpk(acc[1][i]);
            float2 hn = unpk(acc[2][i]);
            float2 hp = h0prev ? *(const float2*)(h0prev + (size_t)b * KPR + col)
                               : make_float2(0.f, 0.f);
            float2 o;
            {
                float r = sigmf(xr.x + hr.x + bh0.x);
                float z = sigmf(xz.x + hz.x + bh1v.x);
                float n = tanhfast(xn.x + r * (hn.x + bh2.x));
                o.x = (1.f - z) * n + z * hp.x;
            }
            {
                float r = sigmf(xr.y + hr.y + bh0.y);
                float z = sigmf(xz.y + hz.y + bh1v.y);
                float n = tanhfast(xn.y + r * (hn.y + bh2.y));
                o.y = (1.f - z) * n + z * hp.y;
            }
            *(float2*)(h0out + (size_t)b * KPR + col) = o;
        }
    }
}

// ---------------- GRU1 fused tile: phases A (Whh1, h) + B (Wih1, x). Same pipeline. ----------------
__device__ __forceinline__ void gru1_tile(
    ull (&Ad)[2][16][64], float (&Ws)[3][3][16][32],
    const float* __restrict__ h1prev, const float* __restrict__ x1in,
    const float* __restrict__ W1, const float* __restrict__ bih1,
    const float* __restrict__ bhh1, float* __restrict__ h1out,
    int tx, int ty, int rowBase, int colBase, int arow, int akq, int wkk, int wc2)
{
    ull acc[4][4];   // 0:r, 1:z, 2:n_h, 3:n_x
#pragma unroll
    for (int g = 0; g < 4; g++)
#pragma unroll
        for (int i = 0; i < 4; i++) acc[g][i] = 0ULL;

    const int ntA = h1prev ? (KPR / 16) : 0;   // 31 or 0
    const int NT = ntA + KPR / 16;             // 62 or 31
    size_t aoff = (size_t)(rowBase + arow) * KPR + akq * 4;
    const float* Wbase = W1 + colBase + wc2 * 2;

    #define APTR(kt) ((kt) < ntA ? h1prev + aoff + (kt) * 16 : x1in + aoff + ((kt) - ntA) * 16)
    #define WROW(kt) ((kt) < ntA ? (size_t)(kt) * 16 : (size_t)KPR + (size_t)((kt) - ntA) * 16)

    // prologue
    float4 aC = *(const float4*)(APTR(0));
    float4 aN1 = *(const float4*)(APTR(1));
#pragma unroll
    for (int g = 0; g < 3; g++)
        cp8(&Ws[0][g][wkk][wc2 * 2], Wbase + (WROW(0) + wkk) * G3P + g * 512);
    cp_commit();
#pragma unroll
    for (int g = 0; g < 3; g++)
        cp8(&Ws[1][g][wkk][wc2 * 2], Wbase + (WROW(1) + wkk) * G3P + g * 512);
    cp_commit();
    {
        float f[4] = {aC.x, aC.y, aC.z, aC.w};
#pragma unroll
        for (int q = 0; q < 4; q++) Ad[0][akq * 4 + q][arow] = dup2(f[q]);
    }
    int sC = 0, sP = 2;
    for (int kt = 0; kt < NT; kt++) {
        float4 aN2;
        if (kt + 2 < NT) aN2 = *(const float4*)(APTR(kt + 2));
        cp_wait1();
        __syncthreads();
        if (kt + 2 < NT) {
#pragma unroll
            for (int g = 0; g < 3; g++)
                cp8(&Ws[sP][g][wkk][wc2 * 2],
                    Wbase + (WROW(kt + 2) + wkk) * G3P + g * 512);
        }
        cp_commit();
        if (kt < ntA) gru_mma16(Ad[kt & 1], Ws[sC], acc[0], acc[1], acc[2], tx, ty);
        else          gru_mma16(Ad[kt & 1], Ws[sC], acc[0], acc[1], acc[3], tx, ty);
        if (kt + 1 < NT) {
            float f[4] = {aN1.x, aN1.y, aN1.z, aN1.w};
#pragma unroll
            for (int q = 0; q < 4; q++) Ad[(kt + 1) & 1][akq * 4 + q][arow] = dup2(f[q]);
        }
        aN1 = aN2;
        sC = (sC == 2) ? 0 : sC + 1;
        sP = (sP == 2) ? 0 : sP + 1;
    }
    #undef APTR
    #undef WROW

    int col = colBase + tx * 2;
    if (col < RECN) {
        float2 bi_r = *(const float2*)(bih1 + 0 * RECN + col);
        float2 bi_z = *(const float2*)(bih1 + 1 * RECN + col);
        float2 bi_n = *(const float2*)(bih1 + 2 * RECN + col);
        float2 bh_r = *(const float2*)(bhh1 + 0 * RECN + col);
        float2 bh_z = *(const float2*)(bhh1 + 1 * RECN + col);
        float2 bh_n = *(const float2*)(bhh1 + 2 * RECN + col);
#pragma unroll
        for (int i = 0; i < 4; i++) {
            int b = rowBase + ty * 4 + i;
            float2 ar = unpk(acc[0][i]);
            float2 az = unpk(acc[1][i]);
            float2 anh = unpk(acc[2][i]);
            float2 anx = unpk(acc[3][i]);
            float2 hp = h1prev ? *(const float2*)(h1prev + (size_t)b * KPR + col)
                               : make_float2(0.f, 0.f);
            float2 o;
            {
                float r = sigmf(ar.x + bi_r.x + bh_r.x);
                float z = sigmf(az.x + bi_z.x + bh_z.x);
                float n = tanhfast(anx.x + bi_n.x + r * (anh.x + bh_n.x));
                o.x = (1.f - z) * n + z * hp.x;
            }
            {
                float r = sigmf(ar.y + bi_r.y + bh_r.y);
                float z = sigmf(az.y + bi_z.y + bh_z.y);
                float n = tanhfast(anx.y + bi_n.y + r * (anh.y + bh_n.y));
                o.y = (1.f - z) * n + z * hp.y;
            }
            *(float2*)(h1out + (size_t)b * KPR + col) = o;
        }
    }
}

// ---------------- persistent kernel: both recurrences, grid barrier per step ----------------
__global__ __launch_bounds__(256, 1)
void gru_persist(const float* __restrict__ xg0v,
                 const float* __restrict__ W0h, const float* __restrict__ bhh0,
                 const float* __restrict__ W1hx, const float* __restrict__ bih1,
                 const float* __restrict__ bhh1,
                 float* __restrict__ X0, float* __restrict__ X1)
{
    __shared__ ull   Ad[2][16][64];         // 16KB
    __shared__ float Ws[3][3][16][32];      // 18KB
    const int tid = threadIdx.x;
    const int tx = tid & 15, ty = tid >> 4;
    const int bid = blockIdx.x;
    const int colBase = (bid & 15) * 32;
    const int rowBase = (bid >> 4) * 64;
    const int arow = tid >> 2, akq = tid & 3;
    const int wkk = tid >> 4, wc2 = tid & 15;

    unsigned gen0 = 0;
    if (tid == 0) gen0 = ld_acq(&g_barGen);   // monotonic base across replays

    for (int s = 0; s <= TN; s++) {
        if (s < TN) {
            gru0_tile(Ad, Ws,
                      (s == 0) ? nullptr : (X0 + (size_t)(s - 1) * BHP),
                      xg0v, W0h, bhh0, X0 + (size_t)s * BHP,
                      tx, ty, rowBase, colBase, arow, akq, wkk, wc2);
        }
        __syncthreads();   // phase boundary: smem reuse between sub-steps
        if (s >= 1) {
            int t1 = s - 1;
            gru1_tile(Ad, Ws,
                      (t1 == 0) ? nullptr : (X1 + (size_t)(t1 - 1) * BHP),
                      X0 + (size_t)t1 * BHP,
                      W1hx, bih1, bhh1, X1 + (size_t)t1 * BHP,
                      tx, ty, rowBase, colBase, arow, akq, wkk, wc2);
        }
        if (s < TN) {
            __syncthreads();
            if (tid == 0) {
                __threadfence();
                unsigned tk = atomicAdd(&g_barCnt, 1u);
                unsigned target = gen0 + (unsigned)s + 1u;
                if (tk == (unsigned)(GRID_P - 1)) {
                    atomicExch(&g_barCnt, 0u);
                    atomicAdd(&g_barGen, 1u);
                } else {
                    while ((int)(ld_acq(&g_barGen) - target) < 0) __nanosleep(64);
                }
                __threadfence();
            }
            __syncthreads();
        }
    }
}

// ---------------- custom GRU cell ----------------
__global__ __launch_bounds__(128)
void cell_all(const float* __restrict__ xg_all,
              const float* __restrict__ Whh,
              const float* __restrict__ bih,
              float* __restrict__ out) {
    __shared__ float W[NC3 * NCN];
    __shared__ float bs[NC3];
    __shared__ float h[NCN], r[NCN], u[NCN];
    __shared__ float e[64];
    int b = blockIdx.x;
    int tid = threadIdx.x;
    for (int i = tid; i < NC3 * NCN; i += 128) W[i] = Whh[i];
    if (tid < NC3) bs[tid] = bih[tid];
    if (tid < NCN) h[tid] = 0.f;
    __syncthreads();

    for (int t = 0; t < TN; t++) {
        const float* xgp = xg_all + ((size_t)t * BATCH + b) * NCP;
        if (tid < 70) {
            float s = 0.f;
#pragma unroll
            for (int k = 0; k < NCN; k++) s += h[k] * W[tid * NCN + k];
            float v = sigmf(xgp[tid] + s + bs[tid]);
            if (tid < NCN) r[tid] = v; else u[tid - NCN] = v;
        }
        __syncthreads();
        float npre = -3.0e38f;
        if (tid < NCN) {
            float s = 0.f;
#pragma unroll
            for (int k = 0; k < NCN; k++) s += r[k] * h[k] * W[(70 + tid) * NCN + k];
            npre = xgp[70 + tid] + s + bs[70 + tid];
        }
        if (tid < 64) e[tid] = (tid < NCN) ? npre : -3.0e38f;
        __syncthreads();
        if (tid < 32) {
            float v = fmaxf(e[tid], e[tid + 32]);
#pragma unroll
            for (int o = 16; o > 0; o >>= 1) v = fmaxf(v, __shfl_xor_sync(0xffffffffu, v, o));
            if (tid == 0) e[0] = v;
        }
        __syncthreads();
        float mx = e[0];
        __syncthreads();
        float ex = 0.f;
        if (tid < NCN) ex = __expf(npre - mx);
        if (tid < 64) e[tid] = (tid < NCN) ? ex : 0.f;
        __syncthreads();
        if (tid < 32) {
            float v = e[tid] + e[tid + 32];
#pragma unroll
            for (int o = 16; o > 0; o >>= 1) v += __shfl_xor_sync(0xffffffffu, v, o);
            if (tid == 0) e[0] = v;
        }
        __syncthreads();
        float sum = e[0];
        float h2 = 0.f;
        if (tid < NCN) {
            float n = ex / sum;
            h2 = (1.f - u[tid]) * n + u[tid] * h[tid];
            out[(size_t)b * (TN * NCN) + t * NCN + tid] = h2;
        }
        __syncthreads();
        if (tid < NCN) h[tid] = h2;
        __syncthreads();
    }
}

// ---------------- launch ----------------
static inline int ceil_div(int a, int b) { return (a + b - 1) / b; }

extern "C" void kernel_launch(void* const* d_in, const int* in_sizes, int n_in,
                              void* d_out, int out_size) {
    const float* z_in     = (const float*)d_in[0];
    const float* W0       = (const float*)d_in[1];
    const float* b0       = (const float*)d_in[2];
    const float* g0       = (const float*)d_in[3];
    const float* beta0    = (const float*)d_in[4];
    const float* W1       = (const float*)d_in[5];
    const float* b1       = (const float*)d_in[6];
    const float* g1       = (const float*)d_in[7];
    const float* beta1    = (const float*)d_in[8];
    const float* gru0_Wih = (const float*)d_in[9];
    const float* gru0_Whh = (const float*)d_in[10];
    const float* gru0_bih = (const float*)d_in[11];
    const float* gru0_bhh = (const float*)d_in[12];
    const float* gru1_Wih = (const float*)d_in[13];
    const float* gru1_Whh = (const float*)d_in[14];
    const float* gru1_bih = (const float*)d_in[15];
    const float* gru1_bhh = (const float*)d_in[16];
    const float* cell_Wih = (const float*)d_in[17];
    const float* cell_Whh = (const float*)d_in[18];
    const float* cell_bih = (const float*)d_in[19];
    float* out = (float*)d_out;

    float *z1, *z2, *xg0, *X0, *X1, *XGc;
    float *WtD0, *WtD1, *Wt0x, *Wt0h, *Wt1hx, *Wtc;
    cudaGetSymbolAddress((void**)&z1,  g_z1);
    cudaGetSymbolAddress((void**)&z2,  g_z2);
    cudaGetSymbolAddress((void**)&xg0, g_xg0);
    cudaGetSymbolAddress((void**)&X0,  g_X0);
    cudaGetSymbolAddress((void**)&X1,  g_X1);
    cudaGetSymbolAddress((void**)&XGc, g_XGc);
    cudaGetSymbolAddress((void**)&WtD0, g_WtD0);
    cudaGetSymbolAddress((void**)&WtD1, g_WtD1);
    cudaGetSymbolAddress((void**)&Wt0x, g_Wt0x);
    cudaGetSymbolAddress((void**)&Wt0h, g_Wt0h);
    cudaGetSymbolAddress((void**)&Wt1hx, g_Wt1hx);
    cudaGetSymbolAddress((void**)&Wtc,  g_Wtc);

    float* Wt1h = Wt1hx;                          // rows [0,496)
    float* Wt1x = Wt1hx + (size_t)KPR * G3P;      // rows [496,992)

    trans_all<<<dim3(48, 16, 7), dim3(32, 8)>>>(
        W0, W1, gru0_Wih, gru0_Whh, gru1_Wih, gru1_Whh, cell_Wih,
        WtD0, WtD1, Wt0x, Wt0h, Wt1x, Wt1h, Wtc);

    gemm_naive<<<dim3(ceil_div(HIDN,128), BATCH/128), 256>>>(
        z_in, WtD0, b0, g0, beta0, z1, BATCH, HIDN, HIDN, HIDN);
    gemm_naive<<<dim3(ceil_div(HIDN,128), BATCH/128), 256>>>(
        z1, WtD1, b1, g1, beta1, z2, BATCH, HIDN, HIDN, KPH);

    gemmP<<<dim3(G3P/128, BATCH/128), 256>>>(
        z2, KPH, KPH, Wt0x, G3P, gru0_bih, 1, RECN, xg0);

    // both recurrences: persistent, 3-stage cp.async pipeline, 120 grid barriers
    gru_persist<<<GRID_P, 256>>>(xg0, Wt0h, gru0_bhh, Wt1hx, gru1_bih, gru1_bhh, X0, X1);

    // cell input gates for all T (no bias)
    gemmP<<<dim3(NCP/128, (TN * BATCH) / 128), 256>>>(
        X1, KPR, KPR, Wtc, NCP, nullptr, 0, NC3, XGc);

    cell_all<<<BATCH, 128>>>(XGc, cell_Whh, cell_bih, out);
}

// round 11
// speedup vs baseline: 1.0055x; 1.0055x over previous
#include <cuda_runtime.h>
#include <stdint.h>

#define BATCH 512
#define HIDN  196
#define RECN  488
#define G3N   1464
#define G3P   1536     // gate-padded: 3 x 512
#define KPH   208      // HIDN padded to mult of 16
#define KPR   496      // RECN padded to mult of 16
#define NCN   35
#define NC3   105
#define NCP   128
#define TN    120
#define BHP   (BATCH*KPR)
#define GRID_P 128

typedef unsigned long long ull;

// ---------------- f32x2 helpers ----------------
__device__ __forceinline__ ull dup2(float x) {
    ull r; asm("mov.b64 %0, {%1, %1};" : "=l"(r) : "f"(x)); return r;
}
__device__ __forceinline__ void fma2(ull& d, ull a, ull b) {
    asm("fma.rn.f32x2 %0, %1, %2, %0;" : "+l"(d) : "l"(a), "l"(b));
}
__device__ __forceinline__ float2 unpk(ull v) {
    float2 r; asm("mov.b64 {%0, %1}, %2;" : "=f"(r.x), "=f"(r.y) : "l"(v)); return r;
}
__device__ __forceinline__ float sigmf(float x) { return 1.f / (1.f + __expf(-x)); }
__device__ __forceinline__ float tanhfast(float x) { return 1.f - 2.f / (__expf(2.f * x) + 1.f); }

__device__ __forceinline__ uint32_t smaddr(const void* p) {
    return (uint32_t)__cvta_generic_to_shared(p);
}
__device__ __forceinline__ void cp16(void* dst, const void* src) {
    asm volatile("cp.async.ca.shared.global [%0], [%1], 16;" :: "r"(smaddr(dst)), "l"(src));
}
__device__ __forceinline__ void cp8(void* dst, const void* src) {
    asm volatile("cp.async.ca.shared.global [%0], [%1], 8;" :: "r"(smaddr(dst)), "l"(src));
}
__device__ __forceinline__ void cp_commit() { asm volatile("cp.async.commit_group;"); }
__device__ __forceinline__ void cp_wait0()  { asm volatile("cp.async.wait_group 0;" ::: "memory"); }
__device__ __forceinline__ void cp_wait1()  { asm volatile("cp.async.wait_group 1;" ::: "memory"); }

__device__ __forceinline__ unsigned ld_acq(unsigned* p) {
    unsigned v;
    asm volatile("ld.acquire.gpu.global.b32 %0, [%1];" : "=r"(v) : "l"(p) : "memory");
    return v;
}

// ---------------- scratch ----------------
__device__ float g_z1 [BATCH*HIDN];
__device__ float g_z2 [BATCH*KPH];
__device__ float g_xg0[(size_t)BATCH*G3P];
__device__ float g_X0 [(size_t)TN*BATCH*KPR];
__device__ float g_X1 [(size_t)TN*BATCH*KPR];
__device__ float g_XGc[(size_t)TN*BATCH*NCP];
__device__ float g_WtD0[HIDN*HIDN];
__device__ float g_WtD1[HIDN*HIDN];
__device__ float g_Wt0x[(size_t)KPH*G3P];
__device__ float g_Wt0h[(size_t)KPR*G3P];
__device__ float g_Wt1hx[(size_t)2*KPR*G3P];   // rows [0,496): Whh1ᵀ, rows [496,992): Wih1ᵀ
__device__ float g_Wtc [(size_t)KPR*NCP];

// grid-barrier state (monotonic generation: replay-safe, never reset)
__device__ unsigned g_barGen = 0;
__device__ unsigned g_barCnt = 0;

// ---------------- fused transpose/pack (7 jobs) ----------------
__global__ void trans_all(
    const float* __restrict__ W0,  const float* __restrict__ W1,
    const float* __restrict__ Wih0,const float* __restrict__ Whh0,
    const float* __restrict__ Wih1,const float* __restrict__ Whh1,
    const float* __restrict__ Wc,
    float* __restrict__ WtD0, float* __restrict__ WtD1,
    float* __restrict__ Wt0x, float* __restrict__ Wt0h,
    float* __restrict__ Wt1x, float* __restrict__ Wt1h,
    float* __restrict__ Wtc)
{
    int j = blockIdx.z;
    const float* src; float* dst;
    int DR, DC, SK, NV, gate;
    switch (j) {
      case 0: src=W0;   dst=WtD0; DR=HIDN; DC=HIDN; SK=HIDN; NV=HIDN; gate=0; break;
      case 1: src=W1;   dst=WtD1; DR=HIDN; DC=HIDN; SK=HIDN; NV=HIDN; gate=0; break;
      case 2: src=Wih0; dst=Wt0x; DR=KPH;  DC=G3P;  SK=HIDN; NV=RECN; gate=1; break;
      case 3: src=Whh0; dst=Wt0h; DR=KPR;  DC=G3P;  SK=RECN; NV=RECN; gate=1; break;
      case 4: src=Wih1; dst=Wt1x; DR=KPR;  DC=G3P;  SK=RECN; NV=RECN; gate=1; break;
      case 5: src=Whh1; dst=Wt1h; DR=KPR;  DC=G3P;  SK=RECN; NV=RECN; gate=1; break;
      default:src=Wc;   dst=Wtc;  DR=KPR;  DC=NCP;  SK=RECN; NV=NC3;  gate=0; break;
    }
    int r0 = blockIdx.y * 32, c0 = blockIdx.x * 32;
    if (r0 >= DR || c0 >= DC) return;
    __shared__ float tile[32][33];
    int tx = threadIdx.x, ty = threadIdx.y;
    for (int i = ty; i < 32; i += 8) {
        int c = c0 + i, k = r0 + tx;
        float v = 0.f;
        if (c < DC && k < SK) {
            int n  = gate ? (c & 511) : c;
            int sr = gate ? ((c >> 9) * RECN + n) : c;
            if (n < NV) v = src[(size_t)sr * SK + k];
        }
        tile[i][tx] = v;
    }
    __syncthreads();
    for (int i = ty; i < 32; i += 8) {
        int r = r0 + i, c = c0 + tx;
        if (r < DR && c < DC) dst[(size_t)r * DC + c] = tile[tx][i];
    }
}

// ---------------- small GEMM for dense+BN ----------------
__global__ __launch_bounds__(256)
void gemm_naive(const float* __restrict__ A, const float* __restrict__ Bt,
                const float* __restrict__ bias, const float* __restrict__ gamma,
                const float* __restrict__ beta, float* __restrict__ C,
                int M, int N, int K, int ldc) {
    __shared__ float As[16][132];
    __shared__ float Bs[16][128];
    int tid = threadIdx.x;
    int tx = tid & 15, ty = tid >> 4;
    int rowBase = blockIdx.y * 128, colBase = blockIdx.x * 128;
    ull acc[8][4];
#pragma unroll
    for (int i = 0; i < 8; i++)
#pragma unroll
        for (int j = 0; j < 4; j++) acc[i][j] = 0ULL;

    for (int k0 = 0; k0 < K; k0 += 16) {
        {
            int kk = tid & 15, m0 = tid >> 4;
#pragma unroll
            for (int l = 0; l < 8; l++) {
                int m = m0 + l * 16;
                float v = 0.f;
                if (k0 + kk < K) v = A[(size_t)(rowBase + m) * K + k0 + kk];
                As[kk][m] = v;
            }
        }
        {
            int c = tid & 127, kb = tid >> 7;
#pragma unroll
            for (int l = 0; l < 8; l++) {
                int kk = kb + l * 2;
                float v = 0.f;
                if ((k0 + kk) < K && (colBase + c) < N)
                    v = Bt[(size_t)(k0 + kk) * N + colBase + c];
                Bs[kk][c] = v;
            }
        }
        __syncthreads();
#pragma unroll
        for (int kk = 0; kk < 16; kk++) {
            float4 av0 = *(const float4*)&As[kk][ty * 8];
            float4 av1 = *(const float4*)&As[kk][ty * 8 + 4];
            ull a2[8];
            a2[0]=dup2(av0.x); a2[1]=dup2(av0.y); a2[2]=dup2(av0.z); a2[3]=dup2(av0.w);
            a2[4]=dup2(av1.x); a2[5]=dup2(av1.y); a2[6]=dup2(av1.z); a2[7]=dup2(av1.w);
            const ulonglong2* bp = (const ulonglong2*)&Bs[kk][tx * 8];
            ulonglong2 bv0 = bp[0], bv1 = bp[1];
            ull b2[4] = {bv0.x, bv0.y, bv1.x, bv1.y};
#pragma unroll
            for (int i = 0; i < 8; i++)
#pragma unroll
                for (int j = 0; j < 4; j++) fma2(acc[i][j], a2[i], b2[j]);
        }
        __syncthreads();
    }
    const float invs = 0.99950037f;   // 1/sqrt(1.001)
#pragma unroll
    for (int i = 0; i < 8; i++) {
        int row = rowBase + ty * 8 + i;
        if (row >= M) continue;
#pragma unroll
        for (int j = 0; j < 4; j++) {
            float2 p = unpk(acc[i][j]);
#pragma unroll
            for (int s = 0; s < 2; s++) {
                int col = colBase + tx * 8 + j * 2 + s;
                if (col < N) {
                    float v = (s == 0) ? p.x : p.y;
                    v += bias[col];
                    v = gamma[col] * (v * invs) + beta[col];
                    C[(size_t)row * ldc + col] = v;
                }
            }
        }
    }
}

// ---------------- pipelined 128x128 GEMM (padded, unguarded hot loop) ----------------
__global__ __launch_bounds__(256, 2)
void gemmP(const float* __restrict__ A, int lda, int KP,
           const float* __restrict__ B, int NP,
           const float* __restrict__ bias, int gate, int Nvalid,
           float* __restrict__ C)
{
    __shared__ float As[2][16][132];
    __shared__ float Bs[2][16][128];
    int tid = threadIdx.x;
    int tx = tid & 15, ty = tid >> 4;
    size_t rowBase = (size_t)blockIdx.y * 128;
    int colBase = blockIdx.x * 128;
    int NT = KP >> 4;

    ull acc[8][4];
#pragma unroll
    for (int i = 0; i < 8; i++)
#pragma unroll
        for (int j = 0; j < 4; j++) acc[i][j] = 0ULL;

    int arow[2], akq[2], bkk[2], bc4[2];
#pragma unroll
    for (int l = 0; l < 2; l++) {
        int idx = tid + l * 256;
        arow[l] = idx >> 2;  akq[l] = idx & 3;
        bkk[l]  = idx >> 5;  bc4[l] = idx & 31;
    }

    float4 a0[2];
#pragma unroll
    for (int l = 0; l < 2; l++)
        a0[l] = *(const float4*)(A + (rowBase + arow[l]) * lda + akq[l] * 4);
#pragma unroll
    for (int l = 0; l < 2; l++)
        cp16(&Bs[0][bkk[l]][bc4[l] * 4], B + (size_t)bkk[l] * NP + colBase + bc4[l] * 4);
    cp_commit();
#pragma unroll
    for (int l = 0; l < 2; l++) {
        float f[4] = {a0[l].x, a0[l].y, a0[l].z, a0[l].w};
#pragma unroll
        for (int q = 0; q < 4; q++) As[0][akq[l] * 4 + q][arow[l]] = f[q];
    }

    for (int kt = 0; kt < NT; kt++) {
        int cb = kt & 1, nb = (kt + 1) & 1;
        float4 an[2];
        bool more = (kt + 1 < NT);
        if (more) {
#pragma unroll
            for (int l = 0; l < 2; l++)
                an[l] = *(const float4*)(A + (rowBase + arow[l]) * lda + (kt + 1) * 16 + akq[l] * 4);
        }
        cp_wait0();
        __syncthreads();
        if (more) {
#pragma unroll
            for (int l = 0; l < 2; l++)
                cp16(&Bs[nb][bkk[l]][bc4[l] * 4],
                     B + (size_t)((kt + 1) * 16 + bkk[l]) * NP + colBase + bc4[l] * 4);
            cp_commit();
        }
#pragma unroll
        for (int kk = 0; kk < 16; kk++) {
            float4 av0 = *(const float4*)&As[cb][kk][ty * 8];
            float4 av1 = *(const float4*)&As[cb][kk][ty * 8 + 4];
            ull a2[8];
            a2[0]=dup2(av0.x); a2[1]=dup2(av0.y); a2[2]=dup2(av0.z); a2[3]=dup2(av0.w);
            a2[4]=dup2(av1.x); a2[5]=dup2(av1.y); a2[6]=dup2(av1.z); a2[7]=dup2(av1.w);
            const ulonglong2* bp = (const ulonglong2*)&Bs[cb][kk][tx * 8];
            ulonglong2 bv0 = bp[0], bv1 = bp[1];
            ull b2[4] = {bv0.x, bv0.y, bv1.x, bv1.y};
#pragma unroll
            for (int i = 0; i < 8; i++)
#pragma unroll
                for (int j = 0; j < 4; j++) fma2(acc[i][j], a2[i], b2[j]);
        }
        __syncthreads();
        if (more) {
#pragma unroll
            for (int l = 0; l < 2; l++) {
                float f[4] = {an[l].x, an[l].y, an[l].z, an[l].w};
#pragma unroll
                for (int q = 0; q < 4; q++) As[nb][akq[l] * 4 + q][arow[l]] = f[q];
            }
        }
    }

#pragma unroll
    for (int i = 0; i < 8; i++) {
        size_t row = rowBase + ty * 8 + i;
#pragma unroll
        for (int j = 0; j < 4; j++) {
            float2 p = unpk(acc[i][j]);
#pragma unroll
            for (int s = 0; s < 2; s++) {
                int col = colBase + tx * 8 + j * 2 + s;
                float v = (s == 0) ? p.x : p.y;
                if (bias) {
                    if (gate) {
                        int n = col & 511;
                        if (n < RECN) v += bias[(col >> 9) * RECN + n];
                    } else if (col < Nvalid) {
                        v += bias[col];
                    }
                }
                C[row * NP + col] = v;
            }
        }
    }
}

// ---------------- 16-k MMA tile, register-pipelined (prefetch kk+1 while fma kk) ----------------
__device__ __forceinline__ void gru_mma16(
    const ull (*Ad)[64], const float (*Ws)[16][32],
    ull (&a0)[4], ull (&a1)[4], ull (&aN)[4], int tx, int ty)
{
    const ulonglong2* ap = (const ulonglong2*)&Ad[0][ty * 4];
    ulonglong2 v0 = ap[0], v1 = ap[1];
    ull w0 = *(const ull*)&Ws[0][0][tx * 2];
    ull w1 = *(const ull*)&Ws[1][0][tx * 2];
    ull w2 = *(const ull*)&Ws[2][0][tx * 2];
#pragma unroll
    for (int kk = 0; kk < 16; kk++) {
        ull a2[4] = {v0.x, v0.y, v1.x, v1.y};
        ull cw0 = w0, cw1 = w1, cw2 = w2;
        if (kk + 1 < 16) {
            const ulonglong2* apn = (const ulonglong2*)&Ad[kk + 1][ty * 4];
            v0 = apn[0]; v1 = apn[1];
            w0 = *(const ull*)&Ws[0][kk + 1][tx * 2];
            w1 = *(const ull*)&Ws[1][kk + 1][tx * 2];
            w2 = *(const ull*)&Ws[2][kk + 1][tx * 2];
        }
#pragma unroll
        for (int i = 0; i < 4; i++) {
            fma2(a0[i], a2[i], cw0);
            fma2(a1[i], a2[i], cw1);
            fma2(aN[i], a2[i], cw2);
        }
    }
}

// ---------------- GRU0 tile: 3-stage W pipeline + 2-ahead A prefetch ----------------
__device__ __forceinline__ void gru0_tile(
    ull (&Ad)[2][16][64], float (&Ws)[3][3][16][32],
    const float* __restrict__ h0prev, const float* __restrict__ xg0v,
    const float* __restrict__ W0, const float* __restrict__ bhh0,
    float* __restrict__ h0out,
    int tx, int ty, int rowBase, int colBase, int arow, int akq, int wkk, int wc2)
{
    ull acc[3][4];
#pragma unroll
    for (int g = 0; g < 3; g++)
#pragma unroll
        for (int i = 0; i < 4; i++) acc[g][i] = 0ULL;

    if (h0prev) {
        const float* Abase = h0prev + (size_t)(rowBase + arow) * KPR + akq * 4;
        const float* Wbase = W0 + colBase + wc2 * 2;
        const int NT = KPR / 16;   // 31

        float4 aC = *(const float4*)(Abase);
        float4 aN1 = *(const float4*)(Abase + 16);
#pragma unroll
        for (int g = 0; g < 3; g++)
            cp8(&Ws[0][g][wkk][wc2 * 2], Wbase + (size_t)wkk * G3P + g * 512);
        cp_commit();
#pragma unroll
        for (int g = 0; g < 3; g++)
            cp8(&Ws[1][g][wkk][wc2 * 2], Wbase + (size_t)(16 + wkk) * G3P + g * 512);
        cp_commit();
        {
            float f[4] = {aC.x, aC.y, aC.z, aC.w};
#pragma unroll
            for (int q = 0; q < 4; q++) Ad[0][akq * 4 + q][arow] = dup2(f[q]);
        }
        int sC = 0, sP = 2;
        for (int kt = 0; kt < NT; kt++) {
            float4 aN2;
            if (kt + 2 < NT) aN2 = *(const float4*)(Abase + (kt + 2) * 16);
            cp_wait1();
            __syncthreads();
            if (kt + 2 < NT) {
#pragma unroll
                for (int g = 0; g < 3; g++)
                    cp8(&Ws[sP][g][wkk][wc2 * 2],
                        Wbase + (size_t)((kt + 2) * 16 + wkk) * G3P + g * 512);
            }
            cp_commit();
            gru_mma16(Ad[kt & 1], Ws[sC], acc[0], acc[1], acc[2], tx, ty);
            if (kt + 1 < NT) {
                float f[4] = {aN1.x, aN1.y, aN1.z, aN1.w};
#pragma unroll
                for (int q = 0; q < 4; q++) Ad[(kt + 1) & 1][akq * 4 + q][arow] = dup2(f[q]);
            }
            aN1 = aN2;
            sC = (sC == 2) ? 0 : sC + 1;
            sP = (sP == 2) ? 0 : sP + 1;
        }
    }
    int col = colBase + tx * 2;
    if (col < RECN) {
        float2 bh0 = *(const float2*)(bhh0 + 0 * RECN + col);
        float2 bh1v = *(const float2*)(bhh0 + 1 * RECN + col);
        float2 bh2 = *(const float2*)(bhh0 + 2 * RECN + col);
#pragma unroll
        for (int i = 0; i < 4; i++) {
            int b = rowBase + ty * 4 + i;
            const float* xgb = xg0v + (size_t)b * G3P;
            float2 xr = *(const float2*)(xgb + 0 * 512 + col);
            float2 xz = *(const float2*)(xgb + 1 * 512 + col);
            float2 xn = *(const float2*)(xgb + 2 * 512 + col);
            float2 hr = unpk(acc[0][i]);
            float2 hz = unpk(acc[1][i]);
            float2 hn = unpk(acc[2][i]);
            float2 hp = h0prev ? *(const float2*)(h0prev + (size_t)b * KPR + col)
                               : make_float2(0.f, 0.f);
            float2 o;
            {
                float r = sigmf(xr.x + hr.x + bh0.x);
                float z = sigmf(xz.x + hz.x + bh1v.x);
                float n = tanhfast(xn.x + r * (hn.x + bh2.x));
                o.x = (1.f - z) * n + z * hp.x;
            }
            {
                float r = sigmf(xr.y + hr.y + bh0.y);
                float z = sigmf(xz.y + hz.y + bh1v.y);
                float n = tanhfast(xn.y + r * (hn.y + bh2.y));
                o.y = (1.f - z) * n + z * hp.y;
            }
            *(float2*)(h0out + (size_t)b * KPR + col) = o;
        }
    }
}

// ---------------- GRU1 fused tile: phases A (Whh1, h) + B (Wih1, x) ----------------
__device__ __forceinline__ void gru1_tile(
    ull (&Ad)[2][16][64], float (&Ws)[3][3][16][32],
    const float* __restrict__ h1prev, const float* __restrict__ x1in,
    const float* __restrict__ W1, const float* __restrict__ bih1,
    const float* __restrict__ bhh1, float* __restrict__ h1out,
    int tx, int ty, int rowBase, int colBase, int arow, int akq, int wkk, int wc2)
{
    ull acc[4][4];   // 0:r, 1:z, 2:n_h, 3:n_x
#pragma unroll
    for (int g = 0; g < 4; g++)
#pragma unroll
        for (int i = 0; i < 4; i++) acc[g][i] = 0ULL;

    const int ntA = h1prev ? (KPR / 16) : 0;   // 31 or 0
    const int NT = ntA + KPR / 16;             // 62 or 31
    size_t aoff = (size_t)(rowBase + arow) * KPR + akq * 4;
    const float* Wbase = W1 + colBase + wc2 * 2;

    #define APTR(kt) ((kt) < ntA ? h1prev + aoff + (kt) * 16 : x1in + aoff + ((kt) - ntA) * 16)
    #define WROW(kt) ((kt) < ntA ? (size_t)(kt) * 16 : (size_t)KPR + (size_t)((kt) - ntA) * 16)

    float4 aC = *(const float4*)(APTR(0));
    float4 aN1 = *(const float4*)(APTR(1));
#pragma unroll
    for (int g = 0; g < 3; g++)
        cp8(&Ws[0][g][wkk][wc2 * 2], Wbase + (WROW(0) + wkk) * G3P + g * 512);
    cp_commit();
#pragma unroll
    for (int g = 0; g < 3; g++)
        cp8(&Ws[1][g][wkk][wc2 * 2], Wbase + (WROW(1) + wkk) * G3P + g * 512);
    cp_commit();
    {
        float f[4] = {aC.x, aC.y, aC.z, aC.w};
#pragma unroll
        for (int q = 0; q < 4; q++) Ad[0][akq * 4 + q][arow] = dup2(f[q]);
    }
    int sC = 0, sP = 2;
    for (int kt = 0; kt < NT; kt++) {
        float4 aN2;
        if (kt + 2 < NT) aN2 = *(const float4*)(APTR(kt + 2));
        cp_wait1();
        __syncthreads();
        if (kt + 2 < NT) {
#pragma unroll
            for (int g = 0; g < 3; g++)
                cp8(&Ws[sP][g][wkk][wc2 * 2],
                    Wbase + (WROW(kt + 2) + wkk) * G3P + g * 512);
        }
        cp_commit();
        if (kt < ntA) gru_mma16(Ad[kt & 1], Ws[sC], acc[0], acc[1], acc[2], tx, ty);
        else          gru_mma16(Ad[kt & 1], Ws[sC], acc[0], acc[1], acc[3], tx, ty);
        if (kt + 1 < NT) {
            float f[4] = {aN1.x, aN1.y, aN1.z, aN1.w};
#pragma unroll
            for (int q = 0; q < 4; q++) Ad[(kt + 1) & 1][akq * 4 + q][arow] = dup2(f[q]);
        }
        aN1 = aN2;
        sC = (sC == 2) ? 0 : sC + 1;
        sP = (sP == 2) ? 0 : sP + 1;
    }
    #undef APTR
    #undef WROW

    int col = colBase + tx * 2;
    if (col < RECN) {
        float2 bi_r = *(const float2*)(bih1 + 0 * RECN + col);
        float2 bi_z = *(const float2*)(bih1 + 1 * RECN + col);
        float2 bi_n = *(const float2*)(bih1 + 2 * RECN + col);
        float2 bh_r = *(const float2*)(bhh1 + 0 * RECN + col);
        float2 bh_z = *(const float2*)(bhh1 + 1 * RECN + col);
        float2 bh_n = *(const float2*)(bhh1 + 2 * RECN + col);
#pragma unroll
        for (int i = 0; i < 4; i++) {
            int b = rowBase + ty * 4 + i;
            float2 ar = unpk(acc[0][i]);
            float2 az = unpk(acc[1][i]);
            float2 anh = unpk(acc[2][i]);
            float2 anx = unpk(acc[3][i]);
            float2 hp = h1prev ? *(const float2*)(h1prev + (size_t)b * KPR + col)
                               : make_float2(0.f, 0.f);
            float2 o;
            {
                float r = sigmf(ar.x + bi_r.x + bh_r.x);
                float z = sigmf(az.x + bi_z.x + bh_z.x);
                float n = tanhfast(anx.x + bi_n.x + r * (anh.x + bh_n.x));
                o.x = (1.f - z) * n + z * hp.x;
            }
            {
                float r = sigmf(ar.y + bi_r.y + bh_r.y);
                float z = sigmf(az.y + bi_z.y + bh_z.y);
                float n = tanhfast(anx.y + bi_n.y + r * (anh.y + bh_n.y));
                o.y = (1.f - z) * n + z * hp.y;
            }
            *(float2*)(h1out + (size_t)b * KPR + col) = o;
        }
    }
}

// ---------------- persistent kernel: xg0 GEMM + both recurrences ----------------
__global__ __launch_bounds__(256, 1)
void gru_persist(const float* __restrict__ z2,
                 const float* __restrict__ W0x, const float* __restrict__ bih0,
                 float* __restrict__ xg0v,
                 const float* __restrict__ W0h, const float* __restrict__ bhh0,
                 const float* __restrict__ W1hx, const float* __restrict__ bih1,
                 const float* __restrict__ bhh1,
                 float* __restrict__ X0, float* __restrict__ X1)
{
    __shared__ ull   Ad[2][16][64];         // 16KB
    __shared__ float Ws[3][3][16][32];      // 18KB
    const int tid = threadIdx.x;
    const int tx = tid & 15, ty = tid >> 4;
    const int bid = blockIdx.x;
    const int colBase = (bid & 15) * 32;
    const int rowBase = (bid >> 4) * 64;
    const int arow = tid >> 2, akq = tid & 3;
    const int wkk = tid >> 4, wc2 = tid & 15;

    unsigned gen0 = 0;
    if (tid == 0) gen0 = ld_acq(&g_barGen);   // monotonic base across replays

    // ---- phase -1: xg0 = z2 @ Wt0x + bih0, for THIS block's tile only ----
    // Each block writes exactly the (64 rows x 3x32 gate-cols) slice that only
    // it reads in the gru0 epilogue -> no grid barrier needed.
    {
        ull acc[3][4];
#pragma unroll
        for (int g = 0; g < 3; g++)
#pragma unroll
            for (int i = 0; i < 4; i++) acc[g][i] = 0ULL;
        const float* Abase = z2 + (size_t)(rowBase + arow) * KPH + akq * 4;
        const float* Wbase = W0x + colBase + wc2 * 2;
        const int NT = KPH / 16;   // 13
        for (int kt = 0; kt < NT; kt++) {
            float4 a = *(const float4*)(Abase + kt * 16);
#pragma unroll
            for (int g = 0; g < 3; g++)
                cp8(&Ws[0][g][wkk][wc2 * 2],
                    Wbase + (size_t)(kt * 16 + wkk) * G3P + g * 512);
            cp_commit();
            {
                float f[4] = {a.x, a.y, a.z, a.w};
#pragma unroll
                for (int q = 0; q < 4; q++) Ad[0][akq * 4 + q][arow] = dup2(f[q]);
            }
            cp_wait0();
            __syncthreads();
            gru_mma16(Ad[0], Ws[0], acc[0], acc[1], acc[2], tx, ty);
            __syncthreads();
        }
        int col = colBase + tx * 2;
        if (col < RECN) {
#pragma unroll
            for (int g = 0; g < 3; g++) {
                float2 bi = *(const float2*)(bih0 + g * RECN + col);
#pragma unroll
                for (int i = 0; i < 4; i++) {
                    int b = rowBase + ty * 4 + i;
                    float2 v = unpk(acc[g][i]);
                    v.x += bi.x; v.y += bi.y;
                    *(float2*)(xg0v + (size_t)b * G3P + g * 512 + col) = v;
                }
            }
        }
        __syncthreads();
    }

    // ---- recurrences: GRU0 step s + fused GRU1 step s-1, grid barrier per step ----
    for (int s = 0; s <= TN; s++) {
        if (s < TN) {
            gru0_tile(Ad, Ws,
                      (s == 0) ? nullptr : (X0 + (size_t)(s - 1) * BHP),
                      xg0v, W0h, bhh0, X0 + (size_t)s * BHP,
                      tx, ty, rowBase, colBase, arow, akq, wkk, wc2);
        }
        __syncthreads();   // phase boundary: smem reuse between sub-steps
        if (s >= 1) {
            int t1 = s - 1;
            gru1_tile(Ad, Ws,
                      (t1 == 0) ? nullptr : (X1 + (size_t)(t1 - 1) * BHP),
                      X0 + (size_t)t1 * BHP,
                      W1hx, bih1, bhh1, X1 + (size_t)t1 * BHP,
                      tx, ty, rowBase, colBase, arow, akq, wkk, wc2);
        }
        if (s < TN) {
            __syncthreads();
            if (tid == 0) {
                __threadfence();
                unsigned tk = atomicAdd(&g_barCnt, 1u);
                unsigned target = gen0 + (unsigned)s + 1u;
                if (tk == (unsigned)(GRID_P - 1)) {
                    atomicExch(&g_barCnt, 0u);
                    atomicAdd(&g_barGen, 1u);
                } else {
                    while ((int)(ld_acq(&g_barGen) - target) < 0) __nanosleep(64);
                }
                __threadfence();
            }
            __syncthreads();
        }
    }
}

// ---------------- custom GRU cell ----------------
__global__ __launch_bounds__(128)
void cell_all(const float* __restrict__ xg_all,
              const float* __restrict__ Whh,
              const float* __restrict__ bih,
              float* __restrict__ out) {
    __shared__ float W[NC3 * NCN];
    __shared__ float bs[NC3];
    __shared__ float h[NCN], r[NCN], u[NCN];
    __shared__ float e[64];
    int b = blockIdx.x;
    int tid = threadIdx.x;
    for (int i = tid; i < NC3 * NCN; i += 128) W[i] = Whh[i];
    if (tid < NC3) bs[tid] = bih[tid];
    if (tid < NCN) h[tid] = 0.f;
    __syncthreads();

    for (int t = 0; t < TN; t++) {
        const float* xgp = xg_all + ((size_t)t * BATCH + b) * NCP;
        if (tid < 70) {
            float s = 0.f;
#pragma unroll
            for (int k = 0; k < NCN; k++) s += h[k] * W[tid * NCN + k];
            float v = sigmf(xgp[tid] + s + bs[tid]);
            if (tid < NCN) r[tid] = v; else u[tid - NCN] = v;
        }
        __syncthreads();
        float npre = -3.0e38f;
        if (tid < NCN) {
            float s = 0.f;
#pragma unroll
            for (int k = 0; k < NCN; k++) s += r[k] * h[k] * W[(70 + tid) * NCN + k];
            npre = xgp[70 + tid] + s + bs[70 + tid];
        }
        if (tid < 64) e[tid] = (tid < NCN) ? npre : -3.0e38f;
        __syncthreads();
        if (tid < 32) {
            float v = fmaxf(e[tid], e[tid + 32]);
#pragma unroll
            for (int o = 16; o > 0; o >>= 1) v = fmaxf(v, __shfl_xor_sync(0xffffffffu, v, o));
            if (tid == 0) e[0] = v;
        }
        __syncthreads();
        float mx = e[0];
        __syncthreads();
        float ex = 0.f;
        if (tid < NCN) ex = __expf(npre - mx);
        if (tid < 64) e[tid] = (tid < NCN) ? ex : 0.f;
        __syncthreads();
        if (tid < 32) {
            float v = e[tid] + e[tid + 32];
#pragma unroll
            for (int o = 16; o > 0; o >>= 1) v += __shfl_xor_sync(0xffffffffu, v, o);
            if (tid == 0) e[0] = v;
        }
        __syncthreads();
        float sum = e[0];
        float h2 = 0.f;
        if (tid < NCN) {
            float n = ex / sum;
            h2 = (1.f - u[tid]) * n + u[tid] * h[tid];
            out[(size_t)b * (TN * NCN) + t * NCN + tid] = h2;
        }
        __syncthreads();
        if (tid < NCN) h[tid] = h2;
        __syncthreads();
    }
}

// ---------------- launch ----------------
static inline int ceil_div(int a, int b) { return (a + b - 1) / b; }

extern "C" void kernel_launch(void* const* d_in, const int* in_sizes, int n_in,
                              void* d_out, int out_size) {
    const float* z_in     = (const float*)d_in[0];
    const float* W0       = (const float*)d_in[1];
    const float* b0       = (const float*)d_in[2];
    const float* g0       = (const float*)d_in[3];
    const float* beta0    = (const float*)d_in[4];
    const float* W1       = (const float*)d_in[5];
    const float* b1       = (const float*)d_in[6];
    const float* g1       = (const float*)d_in[7];
    const float* beta1    = (const float*)d_in[8];
    const float* gru0_Wih = (const float*)d_in[9];
    const float* gru0_Whh = (const float*)d_in[10];
    const float* gru0_bih = (const float*)d_in[11];
    const float* gru0_bhh = (const float*)d_in[12];
    const float* gru1_Wih = (const float*)d_in[13];
    const float* gru1_Whh = (const float*)d_in[14];
    const float* gru1_bih = (const float*)d_in[15];
    const float* gru1_bhh = (const float*)d_in[16];
    const float* cell_Wih = (const float*)d_in[17];
    const float* cell_Whh = (const float*)d_in[18];
    const float* cell_bih = (const float*)d_in[19];
    float* out = (float*)d_out;

    float *z1, *z2, *xg0, *X0, *X1, *XGc;
    float *WtD0, *WtD1, *Wt0x, *Wt0h, *Wt1hx, *Wtc;
    cudaGetSymbolAddress((void**)&z1,  g_z1);
    cudaGetSymbolAddress((void**)&z2,  g_z2);
    cudaGetSymbolAddress((void**)&xg0, g_xg0);
    cudaGetSymbolAddress((void**)&X0,  g_X0);
    cudaGetSymbolAddress((void**)&X1,  g_X1);
    cudaGetSymbolAddress((void**)&XGc, g_XGc);
    cudaGetSymbolAddress((void**)&WtD0, g_WtD0);
    cudaGetSymbolAddress((void**)&WtD1, g_WtD1);
    cudaGetSymbolAddress((void**)&Wt0x, g_Wt0x);
    cudaGetSymbolAddress((void**)&Wt0h, g_Wt0h);
    cudaGetSymbolAddress((void**)&Wt1hx, g_Wt1hx);
    cudaGetSymbolAddress((void**)&Wtc,  g_Wtc);

    float* Wt1h = Wt1hx;                          // rows [0,496)
    float* Wt1x = Wt1hx + (size_t)KPR * G3P;      // rows [496,992)

    trans_all<<<dim3(48, 16, 7), dim3(32, 8)>>>(
        W0, W1, gru0_Wih, gru0_Whh, gru1_Wih, gru1_Whh, cell_Wih,
        WtD0, WtD1, Wt0x, Wt0h, Wt1x, Wt1h, Wtc);

    gemm_naive<<<dim3(ceil_div(HIDN,128), BATCH/128), 256>>>(
        z_in, WtD0, b0, g0, beta0, z1, BATCH, HIDN, HIDN, HIDN);
    gemm_naive<<<dim3(ceil_div(HIDN,128), BATCH/128), 256>>>(
        z1, WtD1, b1, g1, beta1, z2, BATCH, HIDN, HIDN, KPH);

    // xg0 GEMM folded into the persistent kernel (block-local slices)
    gru_persist<<<GRID_P, 256>>>(z2, Wt0x, gru0_bih, xg0,
                                 Wt0h, gru0_bhh, Wt1hx, gru1_bih, gru1_bhh, X0, X1);

    // cell input gates for all T (no bias)
    gemmP<<<dim3(NCP/128, (TN * BATCH) / 128), 256>>>(
        X1, KPR, KPR, Wtc, NCP, nullptr, 0, NC3, XGc);

    cell_all<<<BATCH, 128>>>(XGc, cell_Whh, cell_bih, out);
}

// round 12
// speedup vs baseline: 1.3264x; 1.3192x over previous
#include <cuda_runtime.h>
#include <stdint.h>

#define BATCH 512
#define HIDN  196
#define RECN  488
#define G3N   1464
#define G3P   1536     // gate-padded: 3 x 512
#define KPH   208      // HIDN padded to mult of 16
#define KPR   496      // RECN padded to mult of 16
#define NCN   35
#define NC3   105
#define NCP   128
#define TN    120
#define BHP   (BATCH*KPR)
#define GRID_P 128

typedef unsigned long long ull;

// ---------------- f32x2 helpers ----------------
__device__ __forceinline__ ull dup2(float x) {
    ull r; asm("mov.b64 %0, {%1, %1};" : "=l"(r) : "f"(x)); return r;
}
__device__ __forceinline__ void fma2(ull& d, ull a, ull b) {
    asm("fma.rn.f32x2 %0, %1, %2, %0;" : "+l"(d) : "l"(a), "l"(b));
}
__device__ __forceinline__ float2 unpk(ull v) {
    float2 r; asm("mov.b64 {%0, %1}, %2;" : "=f"(r.x), "=f"(r.y) : "l"(v)); return r;
}
__device__ __forceinline__ float sigmf(float x) { return 1.f / (1.f + __expf(-x)); }
__device__ __forceinline__ float tanhfast(float x) { return 1.f - 2.f / (__expf(2.f * x) + 1.f); }

__device__ __forceinline__ uint32_t smaddr(const void* p) {
    return (uint32_t)__cvta_generic_to_shared(p);
}
__device__ __forceinline__ void cp16(void* dst, const void* src) {
    asm volatile("cp.async.ca.shared.global [%0], [%1], 16;" :: "r"(smaddr(dst)), "l"(src));
}
__device__ __forceinline__ void cp_commit() { asm volatile("cp.async.commit_group;"); }
__device__ __forceinline__ void cp_wait0()  { asm volatile("cp.async.wait_group 0;" ::: "memory"); }
__device__ __forceinline__ void cp_wait1()  { asm volatile("cp.async.wait_group 1;" ::: "memory"); }

__device__ __forceinline__ unsigned ld_acq(unsigned* p) {
    unsigned v;
    asm volatile("ld.acquire.gpu.global.b32 %0, [%1];" : "=r"(v) : "l"(p) : "memory");
    return v;
}

// ---------------- scratch ----------------
__device__ float g_z1 [BATCH*HIDN];
__device__ float g_z2 [BATCH*KPH];
__device__ float g_xg0[(size_t)BATCH*G3P];
__device__ float g_X0 [(size_t)TN*BATCH*KPR];
__device__ float g_X1 [(size_t)TN*BATCH*KPR];
__device__ float g_XGc[(size_t)TN*BATCH*NCP];
__device__ float g_WtD0[HIDN*HIDN];
__device__ float g_WtD1[HIDN*HIDN];
__device__ float g_Wt0x[(size_t)KPH*G3P];
__device__ float g_Wt0h[(size_t)KPR*G3P];
__device__ float g_Wt1hx[(size_t)2*KPR*G3P];   // rows [0,496): Whh1ᵀ, rows [496,992): Wih1ᵀ
__device__ float g_Wtc [(size_t)KPR*NCP];

// grid-barrier state (monotonic generation: replay-safe, never reset)
__device__ unsigned g_barGen = 0;
__device__ unsigned g_barCnt = 0;

// ---------------- fused transpose/pack (7 jobs) ----------------
__global__ void trans_all(
    const float* __restrict__ W0,  const float* __restrict__ W1,
    const float* __restrict__ Wih0,const float* __restrict__ Whh0,
    const float* __restrict__ Wih1,const float* __restrict__ Whh1,
    const float* __restrict__ Wc,
    float* __restrict__ WtD0, float* __restrict__ WtD1,
    float* __restrict__ Wt0x, float* __restrict__ Wt0h,
    float* __restrict__ Wt1x, float* __restrict__ Wt1h,
    float* __restrict__ Wtc)
{
    int j = blockIdx.z;
    const float* src; float* dst;
    int DR, DC, SK, NV, gate;
    switch (j) {
      case 0: src=W0;   dst=WtD0; DR=HIDN; DC=HIDN; SK=HIDN; NV=HIDN; gate=0; break;
      case 1: src=W1;   dst=WtD1; DR=HIDN; DC=HIDN; SK=HIDN; NV=HIDN; gate=0; break;
      case 2: src=Wih0; dst=Wt0x; DR=KPH;  DC=G3P;  SK=HIDN; NV=RECN; gate=1; break;
      case 3: src=Whh0; dst=Wt0h; DR=KPR;  DC=G3P;  SK=RECN; NV=RECN; gate=1; break;
      case 4: src=Wih1; dst=Wt1x; DR=KPR;  DC=G3P;  SK=RECN; NV=RECN; gate=1; break;
      case 5: src=Whh1; dst=Wt1h; DR=KPR;  DC=G3P;  SK=RECN; NV=RECN; gate=1; break;
      default:src=Wc;   dst=Wtc;  DR=KPR;  DC=NCP;  SK=RECN; NV=NC3;  gate=0; break;
    }
    int r0 = blockIdx.y * 32, c0 = blockIdx.x * 32;
    if (r0 >= DR || c0 >= DC) return;
    __shared__ float tile[32][33];
    int tx = threadIdx.x, ty = threadIdx.y;
    for (int i = ty; i < 32; i += 8) {
        int c = c0 + i, k = r0 + tx;
        float v = 0.f;
        if (c < DC && k < SK) {
            int n  = gate ? (c & 511) : c;
            int sr = gate ? ((c >> 9) * RECN + n) : c;
            if (n < NV) v = src[(size_t)sr * SK + k];
        }
        tile[i][tx] = v;
    }
    __syncthreads();
    for (int i = ty; i < 32; i += 8) {
        int r = r0 + i, c = c0 + tx;
        if (r < DR && c < DC) dst[(size_t)r * DC + c] = tile[tx][i];
    }
}

// ---------------- small GEMM for dense+BN ----------------
__global__ __launch_bounds__(256)
void gemm_naive(const float* __restrict__ A, const float* __restrict__ Bt,
                const float* __restrict__ bias, const float* __restrict__ gamma,
                const float* __restrict__ beta, float* __restrict__ C,
                int M, int N, int K, int ldc) {
    __shared__ float As[16][132];
    __shared__ float Bs[16][128];
    int tid = threadIdx.x;
    int tx = tid & 15, ty = tid >> 4;
    int rowBase = blockIdx.y * 128, colBase = blockIdx.x * 128;
    ull acc[8][4];
#pragma unroll
    for (int i = 0; i < 8; i++)
#pragma unroll
        for (int j = 0; j < 4; j++) acc[i][j] = 0ULL;

    for (int k0 = 0; k0 < K; k0 += 16) {
        {
            int kk = tid & 15, m0 = tid >> 4;
#pragma unroll
            for (int l = 0; l < 8; l++) {
                int m = m0 + l * 16;
                float v = 0.f;
                if (k0 + kk < K) v = A[(size_t)(rowBase + m) * K + k0 + kk];
                As[kk][m] = v;
            }
        }
        {
            int c = tid & 127, kb = tid >> 7;
#pragma unroll
            for (int l = 0; l < 8; l++) {
                int kk = kb + l * 2;
                float v = 0.f;
                if ((k0 + kk) < K && (colBase + c) < N)
                    v = Bt[(size_t)(k0 + kk) * N + colBase + c];
                Bs[kk][c] = v;
            }
        }
        __syncthreads();
#pragma unroll
        for (int kk = 0; kk < 16; kk++) {
            float4 av0 = *(const float4*)&As[kk][ty * 8];
            float4 av1 = *(const float4*)&As[kk][ty * 8 + 4];
            ull a2[8];
            a2[0]=dup2(av0.x); a2[1]=dup2(av0.y); a2[2]=dup2(av0.z); a2[3]=dup2(av0.w);
            a2[4]=dup2(av1.x); a2[5]=dup2(av1.y); a2[6]=dup2(av1.z); a2[7]=dup2(av1.w);
            const ulonglong2* bp = (const ulonglong2*)&Bs[kk][tx * 8];
            ulonglong2 bv0 = bp[0], bv1 = bp[1];
            ull b2[4] = {bv0.x, bv0.y, bv1.x, bv1.y};
#pragma unroll
            for (int i = 0; i < 8; i++)
#pragma unroll
                for (int j = 0; j < 4; j++) fma2(acc[i][j], a2[i], b2[j]);
        }
        __syncthreads();
    }
    const float invs = 0.99950037f;   // 1/sqrt(1.001)
#pragma unroll
    for (int i = 0; i < 8; i++) {
        int row = rowBase + ty * 8 + i;
        if (row >= M) continue;
#pragma unroll
        for (int j = 0; j < 4; j++) {
            float2 p = unpk(acc[i][j]);
#pragma unroll
            for (int s = 0; s < 2; s++) {
                int col = colBase + tx * 8 + j * 2 + s;
                if (col < N) {
                    float v = (s == 0) ? p.x : p.y;
                    v += bias[col];
                    v = gamma[col] * (v * invs) + beta[col];
                    C[(size_t)row * ldc + col] = v;
                }
            }
        }
    }
}

// ---------------- pipelined 128x128 GEMM (padded, unguarded hot loop) ----------------
__global__ __launch_bounds__(256, 2)
void gemmP(const float* __restrict__ A, int lda, int KP,
           const float* __restrict__ B, int NP,
           const float* __restrict__ bias, int gate, int Nvalid,
           float* __restrict__ C)
{
    __shared__ float As[2][16][132];
    __shared__ float Bs[2][16][128];
    int tid = threadIdx.x;
    int tx = tid & 15, ty = tid >> 4;
    size_t rowBase = (size_t)blockIdx.y * 128;
    int colBase = blockIdx.x * 128;
    int NT = KP >> 4;

    ull acc[8][4];
#pragma unroll
    for (int i = 0; i < 8; i++)
#pragma unroll
        for (int j = 0; j < 4; j++) acc[i][j] = 0ULL;

    int arow[2], akq[2], bkk[2], bc4[2];
#pragma unroll
    for (int l = 0; l < 2; l++) {
        int idx = tid + l * 256;
        arow[l] = idx >> 2;  akq[l] = idx & 3;
        bkk[l]  = idx >> 5;  bc4[l] = idx & 31;
    }

    float4 a0[2];
#pragma unroll
    for (int l = 0; l < 2; l++)
        a0[l] = *(const float4*)(A + (rowBase + arow[l]) * lda + akq[l] * 4);
#pragma unroll
    for (int l = 0; l < 2; l++)
        cp16(&Bs[0][bkk[l]][bc4[l] * 4], B + (size_t)bkk[l] * NP + colBase + bc4[l] * 4);
    cp_commit();
#pragma unroll
    for (int l = 0; l < 2; l++) {
        float f[4] = {a0[l].x, a0[l].y, a0[l].z, a0[l].w};
#pragma unroll
        for (int q = 0; q < 4; q++) As[0][akq[l] * 4 + q][arow[l]] = f[q];
    }

    for (int kt = 0; kt < NT; kt++) {
        int cb = kt & 1, nb = (kt + 1) & 1;
        float4 an[2];
        bool more = (kt + 1 < NT);
        if (more) {
#pragma unroll
            for (int l = 0; l < 2; l++)
                an[l] = *(const float4*)(A + (rowBase + arow[l]) * lda + (kt + 1) * 16 + akq[l] * 4);
        }
        cp_wait0();
        __syncthreads();
        if (more) {
#pragma unroll
            for (int l = 0; l < 2; l++)
                cp16(&Bs[nb][bkk[l]][bc4[l] * 4],
                     B + (size_t)((kt + 1) * 16 + bkk[l]) * NP + colBase + bc4[l] * 4);
            cp_commit();
        }
#pragma unroll
        for (int kk = 0; kk < 16; kk++) {
            float4 av0 = *(const float4*)&As[cb][kk][ty * 8];
            float4 av1 = *(const float4*)&As[cb][kk][ty * 8 + 4];
            ull a2[8];
            a2[0]=dup2(av0.x); a2[1]=dup2(av0.y); a2[2]=dup2(av0.z); a2[3]=dup2(av0.w);
            a2[4]=dup2(av1.x); a2[5]=dup2(av1.y); a2[6]=dup2(av1.z); a2[7]=dup2(av1.w);
            const ulonglong2* bp = (const ulonglong2*)&Bs[cb][kk][tx * 8];
            ulonglong2 bv0 = bp[0], bv1 = bp[1];
            ull b2[4] = {bv0.x, bv0.y, bv1.x, bv1.y};
#pragma unroll
            for (int i = 0; i < 8; i++)
#pragma unroll
                for (int j = 0; j < 4; j++) fma2(acc[i][j], a2[i], b2[j]);
        }
        __syncthreads();
        if (more) {
#pragma unroll
            for (int l = 0; l < 2; l++) {
                float f[4] = {an[l].x, an[l].y, an[l].z, an[l].w};
#pragma unroll
                for (int q = 0; q < 4; q++) As[nb][akq[l] * 4 + q][arow[l]] = f[q];
            }
        }
    }

#pragma unroll
    for (int i = 0; i < 8; i++) {
        size_t row = rowBase + ty * 8 + i;
#pragma unroll
        for (int j = 0; j < 4; j++) {
            float2 p = unpk(acc[i][j]);
#pragma unroll
            for (int s = 0; s < 2; s++) {
                int col = colBase + tx * 8 + j * 2 + s;
                float v = (s == 0) ? p.x : p.y;
                if (bias) {
                    if (gate) {
                        int n = col & 511;
                        if (n < RECN) v += bias[(col >> 9) * RECN + n];
                    } else if (col < Nvalid) {
                        v += bias[col];
                    }
                }
                C[row * NP + col] = v;
            }
        }
    }
}

// ================= persistent recurrence: 128 threads, row-pair packed =================
// Block tile: 64 rows x 32 cols (x3 gates). Thread: 8 rows (4 packed pairs) x 2 cols x 3 gates.
// A stored UNDUP'D in smem (float); row-pairs come free via reinterpret; W scalars reg-dup'd.

// 16-k MMA micro-tile. acc[g][rp][c] where rp = packed row-pair, c = col 0/1.
__device__ __forceinline__ void mma16_rp(
    const float (*Ad)[64], const float (*Ws)[16][32],
    ull (&a0)[4][2], ull (&a1)[4][2], ull (&aN)[4][2], int tx, int ty)
{
    ulonglong2 p01 = *(const ulonglong2*)&Ad[0][ty * 8];
    ulonglong2 p23 = *(const ulonglong2*)&Ad[0][ty * 8 + 4];
    float w0a = Ws[0][0][tx * 2], w0b = Ws[0][0][tx * 2 + 1];
    float w1a = Ws[1][0][tx * 2], w1b = Ws[1][0][tx * 2 + 1];
    float w2a = Ws[2][0][tx * 2], w2b = Ws[2][0][tx * 2 + 1];
#pragma unroll
    for (int kk = 0; kk < 16; kk++) {
        ull ap[4] = {p01.x, p01.y, p23.x, p23.y};
        ull d0a = dup2(w0a), d0b = dup2(w0b);
        ull d1a = dup2(w1a), d1b = dup2(w1b);
        ull d2a = dup2(w2a), d2b = dup2(w2b);
        if (kk + 1 < 16) {
            p01 = *(const ulonglong2*)&Ad[kk + 1][ty * 8];
            p23 = *(const ulonglong2*)&Ad[kk + 1][ty * 8 + 4];
            w0a = Ws[0][kk + 1][tx * 2]; w0b = Ws[0][kk + 1][tx * 2 + 1];
            w1a = Ws[1][kk + 1][tx * 2]; w1b = Ws[1][kk + 1][tx * 2 + 1];
            w2a = Ws[2][kk + 1][tx * 2]; w2b = Ws[2][kk + 1][tx * 2 + 1];
        }
#pragma unroll
        for (int rp = 0; rp < 4; rp++) {
            fma2(a0[rp][0], ap[rp], d0a); fma2(a0[rp][1], ap[rp], d0b);
            fma2(a1[rp][0], ap[rp], d1a); fma2(a1[rp][1], ap[rp], d1b);
            fma2(aN[rp][0], ap[rp], d2a); fma2(aN[rp][1], ap[rp], d2b);
        }
    }
}

// A-tile store: thread writes 8 undup'd floats into Ad[buf][ak8+q][arow]
__device__ __forceinline__ void storeA(float (*Ad)[64], float4 c0, float4 c1,
                                       int ak8, int arow) {
    float f[8] = {c0.x, c0.y, c0.z, c0.w, c1.x, c1.y, c1.z, c1.w};
#pragma unroll
    for (int q = 0; q < 8; q++) Ad[ak8 + q][arow] = f[q];
}

// ---------------- GRU0 tile: 3-stage W pipeline + 2-ahead A prefetch ----------------
__device__ __forceinline__ void gru0_tile(
    float (&Ad)[2][16][64], float (&Ws)[3][3][16][32],
    const float* __restrict__ h0prev, const float* __restrict__ xg0v,
    const float* __restrict__ W0, const float* __restrict__ bhh0,
    float* __restrict__ h0out,
    int tx, int ty, int rowBase, int colBase, int arow, int ak8, int wkk, int wc4)
{
    ull aR[4][2], aZ[4][2], aN[4][2];
#pragma unroll
    for (int i = 0; i < 4; i++)
#pragma unroll
        for (int j = 0; j < 2; j++) { aR[i][j] = 0ULL; aZ[i][j] = 0ULL; aN[i][j] = 0ULL; }

    if (h0prev) {
        const float* Abase = h0prev + (size_t)(rowBase + arow) * KPR + ak8;
        const float* Wb = W0 + colBase + wc4 * 4;
        const int NT = KPR / 16;   // 31

        float4 c0 = *(const float4*)(Abase);
        float4 c1 = *(const float4*)(Abase + 4);
        float4 n0 = *(const float4*)(Abase + 16);
        float4 n1 = *(const float4*)(Abase + 20);
#pragma unroll
        for (int g = 0; g < 3; g++)
            cp16(&Ws[0][g][wkk][wc4 * 4], Wb + (size_t)wkk * G3P + g * 512);
        cp_commit();
#pragma unroll
        for (int g = 0; g < 3; g++)
            cp16(&Ws[1][g][wkk][wc4 * 4], Wb + (size_t)(16 + wkk) * G3P + g * 512);
        cp_commit();
        storeA(Ad[0], c0, c1, ak8, arow);

        int sC = 0, sP = 2;
        for (int kt = 0; kt < NT; kt++) {
            float4 m0, m1;
            if (kt + 2 < NT) {
                m0 = *(const float4*)(Abase + (kt + 2) * 16);
                m1 = *(const float4*)(Abase + (kt + 2) * 16 + 4);
            }
            cp_wait1();
            __syncthreads();
            if (kt + 2 < NT) {
#pragma unroll
                for (int g = 0; g < 3; g++)
                    cp16(&Ws[sP][g][wkk][wc4 * 4],
                         Wb + (size_t)((kt + 2) * 16 + wkk) * G3P + g * 512);
            }
            cp_commit();
            mma16_rp(Ad[kt & 1], Ws[sC], aR, aZ, aN, tx, ty);
            if (kt + 1 < NT) storeA(Ad[(kt + 1) & 1], n0, n1, ak8, arow);
            n0 = m0; n1 = m1;
            sC = (sC == 2) ? 0 : sC + 1;
            sP = (sP == 2) ? 0 : sP + 1;
        }
    }
    int col = colBase + tx * 2;
    if (col < RECN) {
        float2 bh_r = *(const float2*)(bhh0 + 0 * RECN + col);
        float2 bh_z = *(const float2*)(bhh0 + 1 * RECN + col);
        float2 bh_n = *(const float2*)(bhh0 + 2 * RECN + col);
#pragma unroll
        for (int rp = 0; rp < 4; rp++) {
            float2 r0 = unpk(aR[rp][0]), r1 = unpk(aR[rp][1]);
            float2 z0 = unpk(aZ[rp][0]), z1 = unpk(aZ[rp][1]);
            float2 n0v = unpk(aN[rp][0]), n1v = unpk(aN[rp][1]);
#pragma unroll
            for (int h = 0; h < 2; h++) {
                int b = rowBase + ty * 8 + rp * 2 + h;
                float2 hr = h ? make_float2(r0.y, r1.y) : make_float2(r0.x, r1.x);
                float2 hz = h ? make_float2(z0.y, z1.y) : make_float2(z0.x, z1.x);
                float2 hn = h ? make_float2(n0v.y, n1v.y) : make_float2(n0v.x, n1v.x);
                const float* xgb = xg0v + (size_t)b * G3P;
                float2 xr = *(const float2*)(xgb + 0 * 512 + col);
                float2 xz = *(const float2*)(xgb + 1 * 512 + col);
                float2 xn = *(const float2*)(xgb + 2 * 512 + col);
                float2 hp = h0prev ? *(const float2*)(h0prev + (size_t)b * KPR + col)
                                   : make_float2(0.f, 0.f);
                float2 o;
                {
                    float r = sigmf(xr.x + hr.x + bh_r.x);
                    float z = sigmf(xz.x + hz.x + bh_z.x);
                    float n = tanhfast(xn.x + r * (hn.x + bh_n.x));
                    o.x = (1.f - z) * n + z * hp.x;
                }
                {
                    float r = sigmf(xr.y + hr.y + bh_r.y);
                    float z = sigmf(xz.y + hz.y + bh_z.y);
                    float n = tanhfast(xn.y + r * (hn.y + bh_n.y));
                    o.y = (1.f - z) * n + z * hp.y;
                }
                *(float2*)(h0out + (size_t)b * KPR + col) = o;
            }
        }
    }
}

// ---------------- GRU1 fused tile: phases A (Whh1, h) + B (Wih1, x) ----------------
__device__ __forceinline__ void gru1_tile(
    float (&Ad)[2][16][64], float (&Ws)[3][3][16][32],
    const float* __restrict__ h1prev, const float* __restrict__ x1in,
    const float* __restrict__ W1, const float* __restrict__ bih1,
    const float* __restrict__ bhh1, float* __restrict__ h1out,
    int tx, int ty, int rowBase, int colBase, int arow, int ak8, int wkk, int wc4)
{
    ull aR[4][2], aZ[4][2], aNh[4][2], aNx[4][2];
#pragma unroll
    for (int i = 0; i < 4; i++)
#pragma unroll
        for (int j = 0; j < 2; j++) {
            aR[i][j] = 0ULL; aZ[i][j] = 0ULL; aNh[i][j] = 0ULL; aNx[i][j] = 0ULL;
        }

    const int ntA = h1prev ? (KPR / 16) : 0;   // 31 or 0
    const int NT = ntA + KPR / 16;             // 62 or 31
    size_t aoff = (size_t)(rowBase + arow) * KPR + ak8;
    const float* Wb = W1 + colBase + wc4 * 4;

    #define APTR(kt) ((kt) < ntA ? h1prev + aoff + (kt) * 16 : x1in + aoff + ((kt) - ntA) * 16)
    #define WROW(kt) ((kt) < ntA ? (size_t)(kt) * 16 : (size_t)KPR + (size_t)((kt) - ntA) * 16)

    float4 c0 = *(const float4*)(APTR(0));
    float4 c1 = *(const float4*)(APTR(0) + 4);
    float4 n0 = *(const float4*)(APTR(1));
    float4 n1 = *(const float4*)(APTR(1) + 4);
#pragma unroll
    for (int g = 0; g < 3; g++)
        cp16(&Ws[0][g][wkk][wc4 * 4], Wb + (WROW(0) + wkk) * G3P + g * 512);
    cp_commit();
#pragma unroll
    for (int g = 0; g < 3; g++)
        cp16(&Ws[1][g][wkk][wc4 * 4], Wb + (WROW(1) + wkk) * G3P + g * 512);
    cp_commit();
    storeA(Ad[0], c0, c1, ak8, arow);

    int sC = 0, sP = 2;
    for (int kt = 0; kt < NT; kt++) {
        float4 m0, m1;
        if (kt + 2 < NT) {
            m0 = *(const float4*)(APTR(kt + 2));
            m1 = *(const float4*)(APTR(kt + 2) + 4);
        }
        cp_wait1();
        __syncthreads();
        if (kt + 2 < NT) {
#pragma unroll
            for (int g = 0; g < 3; g++)
                cp16(&Ws[sP][g][wkk][wc4 * 4],
                     Wb + (WROW(kt + 2) + wkk) * G3P + g * 512);
        }
        cp_commit();
        if (kt < ntA) mma16_rp(Ad[kt & 1], Ws[sC], aR, aZ, aNh, tx, ty);
        else          mma16_rp(Ad[kt & 1], Ws[sC], aR, aZ, aNx, tx, ty);
        if (kt + 1 < NT) storeA(Ad[(kt + 1) & 1], n0, n1, ak8, arow);
        n0 = m0; n1 = m1;
        sC = (sC == 2) ? 0 : sC + 1;
        sP = (sP == 2) ? 0 : sP + 1;
    }
    #undef APTR
    #undef WROW

    int col = colBase + tx * 2;
    if (col < RECN) {
        float2 bi_r = *(const float2*)(bih1 + 0 * RECN + col);
        float2 bi_z = *(const float2*)(bih1 + 1 * RECN + col);
        float2 bi_n = *(const float2*)(bih1 + 2 * RECN + col);
        float2 bh_r = *(const float2*)(bhh1 + 0 * RECN + col);
        float2 bh_z = *(const float2*)(bhh1 + 1 * RECN + col);
        float2 bh_n = *(const float2*)(bhh1 + 2 * RECN + col);
#pragma unroll
        for (int rp = 0; rp < 4; rp++) {
            float2 r0 = unpk(aR[rp][0]),  r1 = unpk(aR[rp][1]);
            float2 z0 = unpk(aZ[rp][0]),  z1 = unpk(aZ[rp][1]);
            float2 h0v = unpk(aNh[rp][0]), h1v = unpk(aNh[rp][1]);
            float2 x0v = unpk(aNx[rp][0]), x1v = unpk(aNx[rp][1]);
#pragma unroll
            for (int h = 0; h < 2; h++) {
                int b = rowBase + ty * 8 + rp * 2 + h;
                float2 ar = h ? make_float2(r0.y, r1.y) : make_float2(r0.x, r1.x);
                float2 az = h ? make_float2(z0.y, z1.y) : make_float2(z0.x, z1.x);
                float2 anh = h ? make_float2(h0v.y, h1v.y) : make_float2(h0v.x, h1v.x);
                float2 anx = h ? make_float2(x0v.y, x1v.y) : make_float2(x0v.x, x1v.x);
                float2 hp = h1prev ? *(const float2*)(h1prev + (size_t)b * KPR + col)
                                   : make_float2(0.f, 0.f);
                float2 o;
                {
                    float r = sigmf(ar.x + bi_r.x + bh_r.x);
                    float z = sigmf(az.x + bi_z.x + bh_z.x);
                    float n = tanhfast(anx.x + bi_n.x + r * (anh.x + bh_n.x));
                    o.x = (1.f - z) * n + z * hp.x;
                }
                {
                    float r = sigmf(ar.y + bi_r.y + bh_r.y);
                    float z = sigmf(az.y + bi_z.y + bh_z.y);
                    float n = tanhfast(anx.y + bi_n.y + r * (anh.y + bh_n.y));
                    o.y = (1.f - z) * n + z * hp.y;
                }
                *(float2*)(h1out + (size_t)b * KPR + col) = o;
            }
        }
    }
}

// ---------------- persistent kernel: xg0 GEMM + both recurrences ----------------
__global__ __launch_bounds__(128, 1)
void gru_persist(const float* __restrict__ z2,
                 const float* __restrict__ W0x, const float* __restrict__ bih0,
                 float* __restrict__ xg0v,
                 const float* __restrict__ W0h, const float* __restrict__ bhh0,
                 const float* __restrict__ W1hx, const float* __restrict__ bih1,
                 const float* __restrict__ bhh1,
                 float* __restrict__ X0, float* __restrict__ X1)
{
    __shared__ float Ad[2][16][64];         // 8KB (undup'd A)
    __shared__ float Ws[3][3][16][32];      // 18KB
    const int tid = threadIdx.x;
    const int tx = tid & 15, ty = tid >> 4;       // ty 0..7 -> 8 rows each
    const int bid = blockIdx.x;
    const int colBase = (bid & 15) * 32;
    const int rowBase = (bid >> 4) * 64;
    const int arow = tid >> 1, ak8 = (tid & 1) * 8;   // A loader: 64 rows x 2 k-halves
    const int wkk = tid >> 3, wc4 = tid & 7;          // W loader: 16 kk x 8 col-quads

    unsigned gen0 = 0;
    if (tid == 0) gen0 = ld_acq(&g_barGen);   // monotonic base across replays

    // ---- phase -1: xg0 = z2 @ Wt0x + bih0, block-local slice (no grid barrier needed) ----
    {
        ull aR[4][2], aZ[4][2], aN[4][2];
#pragma unroll
        for (int i = 0; i < 4; i++)
#pragma unroll
            for (int j = 0; j < 2; j++) { aR[i][j] = 0ULL; aZ[i][j] = 0ULL; aN[i][j] = 0ULL; }
        const float* Abase = z2 + (size_t)(rowBase + arow) * KPH + ak8;
        const float* Wb = W0x + colBase + wc4 * 4;
        const int NT = KPH / 16;   // 13
        for (int kt = 0; kt < NT; kt++) {
            float4 c0 = *(const float4*)(Abase + kt * 16);
            float4 c1 = *(const float4*)(Abase + kt * 16 + 4);
#pragma unroll
            for (int g = 0; g < 3; g++)
                cp16(&Ws[0][g][wkk][wc4 * 4],
                     Wb + (size_t)(kt * 16 + wkk) * G3P + g * 512);
            cp_commit();
            storeA(Ad[0], c0, c1, ak8, arow);
            cp_wait0();
            __syncthreads();
            mma16_rp(Ad[0], Ws[0], aR, aZ, aN, tx, ty);
            __syncthreads();
        }
        int col = colBase + tx * 2;
        if (col < RECN) {
            float2 b0v = *(const float2*)(bih0 + 0 * RECN + col);
            float2 b1v = *(const float2*)(bih0 + 1 * RECN + col);
            float2 b2v = *(const float2*)(bih0 + 2 * RECN + col);
#pragma unroll
            for (int rp = 0; rp < 4; rp++) {
                float2 g0c0 = unpk(aR[rp][0]), g0c1 = unpk(aR[rp][1]);
                float2 g1c0 = unpk(aZ[rp][0]), g1c1 = unpk(aZ[rp][1]);
                float2 g2c0 = unpk(aN[rp][0]), g2c1 = unpk(aN[rp][1]);
#pragma unroll
                for (int h = 0; h < 2; h++) {
                    int b = rowBase + ty * 8 + rp * 2 + h;
                    float2 v0 = h ? make_float2(g0c0.y, g0c1.y) : make_float2(g0c0.x, g0c1.x);
                    float2 v1 = h ? make_float2(g1c0.y, g1c1.y) : make_float2(g1c0.x, g1c1.x);
                    float2 v2 = h ? make_float2(g2c0.y, g2c1.y) : make_float2(g2c0.x, g2c1.x);
                    v0.x += b0v.x; v0.y += b0v.y;
                    v1.x += b1v.x; v1.y += b1v.y;
                    v2.x += b2v.x; v2.y += b2v.y;
                    *(float2*)(xg0v + (size_t)b * G3P + 0 * 512 + col) = v0;
                    *(float2*)(xg0v + (size_t)b * G3P + 1 * 512 + col) = v1;
                    *(float2*)(xg0v + (size_t)b * G3P + 2 * 512 + col) = v2;
                }
            }
        }
        __syncthreads();
    }

    // ---- recurrences: GRU0 step s + fused GRU1 step s-1, grid barrier per step ----
    for (int s = 0; s <= TN; s++) {
        if (s < TN) {
            gru0_tile(Ad, Ws,
                      (s == 0) ? nullptr : (X0 + (size_t)(s - 1) * BHP),
                      xg0v, W0h, bhh0, X0 + (size_t)s * BHP,
                      tx, ty, rowBase, colBase, arow, ak8, wkk, wc4);
        }
        __syncthreads();   // phase boundary: smem reuse between sub-steps
        if (s >= 1) {
            int t1 = s - 1;
            gru1_tile(Ad, Ws,
                      (t1 == 0) ? nullptr : (X1 + (size_t)(t1 - 1) * BHP),
                      X0 + (size_t)t1 * BHP,
                      W1hx, bih1, bhh1, X1 + (size_t)t1 * BHP,
                      tx, ty, rowBase, colBase, arow, ak8, wkk, wc4);
        }
        if (s < TN) {
            __syncthreads();
            if (tid == 0) {
                __threadfence();
                unsigned tk = atomicAdd(&g_barCnt, 1u);
                unsigned target = gen0 + (unsigned)s + 1u;
                if (tk == (unsigned)(GRID_P - 1)) {
                    atomicExch(&g_barCnt, 0u);
                    atomicAdd(&g_barGen, 1u);
                } else {
                    while ((int)(ld_acq(&g_barGen) - target) < 0) __nanosleep(64);
                }
                __threadfence();
            }
            __syncthreads();
        }
    }
}

// ---------------- custom GRU cell ----------------
__global__ __launch_bounds__(128)
void cell_all(const float* __restrict__ xg_all,
              const float* __restrict__ Whh,
              const float* __restrict__ bih,
              float* __restrict__ out) {
    __shared__ float W[NC3 * NCN];
    __shared__ float bs[NC3];
    __shared__ float h[NCN], r[NCN], u[NCN];
    __shared__ float e[64];
    int b = blockIdx.x;
    int tid = threadIdx.x;
    for (int i = tid; i < NC3 * NCN; i += 128) W[i] = Whh[i];
    if (tid < NC3) bs[tid] = bih[tid];
    if (tid < NCN) h[tid] = 0.f;
    __syncthreads();

    for (int t = 0; t < TN; t++) {
        const float* xgp = xg_all + ((size_t)t * BATCH + b) * NCP;
        if (tid < 70) {
            float s = 0.f;
#pragma unroll
            for (int k = 0; k < NCN; k++) s += h[k] * W[tid * NCN + k];
            float v = sigmf(xgp[tid] + s + bs[tid]);
            if (tid < NCN) r[tid] = v; else u[tid - NCN] = v;
        }
        __syncthreads();
        float npre = -3.0e38f;
        if (tid < NCN) {
            float s = 0.f;
#pragma unroll
            for (int k = 0; k < NCN; k++) s += r[k] * h[k] * W[(70 + tid) * NCN + k];
            npre = xgp[70 + tid] + s + bs[70 + tid];
        }
        if (tid < 64) e[tid] = (tid < NCN) ? npre : -3.0e38f;
        __syncthreads();
        if (tid < 32) {
            float v = fmaxf(e[tid], e[tid + 32]);
#pragma unroll
            for (int o = 16; o > 0; o >>= 1) v = fmaxf(v, __shfl_xor_sync(0xffffffffu, v, o));
            if (tid == 0) e[0] = v;
        }
        __syncthreads();
        float mx = e[0];
        __syncthreads();
        float ex = 0.f;
        if (tid < NCN) ex = __expf(npre - mx);
        if (tid < 64) e[tid] = (tid < NCN) ? ex : 0.f;
        __syncthreads();
        if (tid < 32) {
            float v = e[tid] + e[tid + 32];
#pragma unroll
            for (int o = 16; o > 0; o >>= 1) v += __shfl_xor_sync(0xffffffffu, v, o);
            if (tid == 0) e[0] = v;
        }
        __syncthreads();
        float sum = e[0];
        float h2 = 0.f;
        if (tid < NCN) {
            float n = ex / sum;
            h2 = (1.f - u[tid]) * n + u[tid] * h[tid];
            out[(size_t)b * (TN * NCN) + t * NCN + tid] = h2;
        }
        __syncthreads();
        if (tid < NCN) h[tid] = h2;
        __syncthreads();
    }
}

// ---------------- launch ----------------
static inline int ceil_div(int a, int b) { return (a + b - 1) / b; }

extern "C" void kernel_launch(void* const* d_in, const int* in_sizes, int n_in,
                              void* d_out, int out_size) {
    const float* z_in     = (const float*)d_in[0];
    const float* W0       = (const float*)d_in[1];
    const float* b0       = (const float*)d_in[2];
    const float* g0       = (const float*)d_in[3];
    const float* beta0    = (const float*)d_in[4];
    const float* W1       = (const float*)d_in[5];
    const float* b1       = (const float*)d_in[6];
    const float* g1       = (const float*)d_in[7];
    const float* beta1    = (const float*)d_in[8];
    const float* gru0_Wih = (const float*)d_in[9];
    const float* gru0_Whh = (const float*)d_in[10];
    const float* gru0_bih = (const float*)d_in[11];
    const float* gru0_bhh = (const float*)d_in[12];
    const float* gru1_Wih = (const float*)d_in[13];
    const float* gru1_Whh = (const float*)d_in[14];
    const float* gru1_bih = (const float*)d_in[15];
    const float* gru1_bhh = (const float*)d_in[16];
    const float* cell_Wih = (const float*)d_in[17];
    const float* cell_Whh = (const float*)d_in[18];
    const float* cell_bih = (const float*)d_in[19];
    float* out = (float*)d_out;

    float *z1, *z2, *xg0, *X0, *X1, *XGc;
    float *WtD0, *WtD1, *Wt0x, *Wt0h, *Wt1hx, *Wtc;
    cudaGetSymbolAddress((void**)&z1,  g_z1);
    cudaGetSymbolAddress((void**)&z2,  g_z2);
    cudaGetSymbolAddress((void**)&xg0, g_xg0);
    cudaGetSymbolAddress((void**)&X0,  g_X0);
    cudaGetSymbolAddress((void**)&X1,  g_X1);
    cudaGetSymbolAddress((void**)&XGc, g_XGc);
    cudaGetSymbolAddress((void**)&WtD0, g_WtD0);
    cudaGetSymbolAddress((void**)&WtD1, g_WtD1);
    cudaGetSymbolAddress((void**)&Wt0x, g_Wt0x);
    cudaGetSymbolAddress((void**)&Wt0h, g_Wt0h);
    cudaGetSymbolAddress((void**)&Wt1hx, g_Wt1hx);
    cudaGetSymbolAddress((void**)&Wtc,  g_Wtc);

    float* Wt1h = Wt1hx;                          // rows [0,496)
    float* Wt1x = Wt1hx + (size_t)KPR * G3P;      // rows [496,992)

    trans_all<<<dim3(48, 16, 7), dim3(32, 8)>>>(
        W0, W1, gru0_Wih, gru0_Whh, gru1_Wih, gru1_Whh, cell_Wih,
        WtD0, WtD1, Wt0x, Wt0h, Wt1x, Wt1h, Wtc);

    gemm_naive<<<dim3(ceil_div(HIDN,128), BATCH/128), 256>>>(
        z_in, WtD0, b0, g0, beta0, z1, BATCH, HIDN, HIDN, HIDN);
    gemm_naive<<<dim3(ceil_div(HIDN,128), BATCH/128), 256>>>(
        z1, WtD1, b1, g1, beta1, z2, BATCH, HIDN, HIDN, KPH);

    // xg0 GEMM folded into the persistent kernel; 128 threads, row-pair packed MMA
    gru_persist<<<GRID_P, 128>>>(z2, Wt0x, gru0_bih, xg0,
                                 Wt0h, gru0_bhh, Wt1hx, gru1_bih, gru1_bhh, X0, X1);

    // cell input gates for all T (no bias)
    gemmP<<<dim3(NCP/128, (TN * BATCH) / 128), 256>>>(
        X1, KPR, KPR, Wtc, NCP, nullptr, 0, NC3, XGc);

    cell_all<<<BATCH, 128>>>(XGc, cell_Whh, cell_bih, out);
}